// round 7
// baseline (speedup 1.0000x reference)
#include <cuda_runtime.h>
#include <math.h>
#include <stdint.h>

#define D_MODEL 1024
#define D_FF    4096
#define NE      8
#define T_TOK   4096
#define MAXROWS 9216      // 8192 rows + 8 experts * 128-pad
#define MAXTILES 72

// GEMM tiling: CTA 128(M) x 256(N) x 32(K), 256 thr, warps 2x4 of 64x64
#define NSTAGE 3
#define AW     4608                 // A stage words: 128 rows * 36
#define BW     9216                 // B stage words: 256 rows * 36 (k-major)
#define AB     (AW * 4)             // 18432 B
#define STAGE_BYTES ((AW + BW) * 4) // 55296 B
#define SMEM_TOTAL (NSTAGE * STAGE_BYTES)  // 165888 B

// ---------------- scratch (static device memory: allocation-free) -------------
__device__ float g_act[(size_t)MAXROWS * D_FF];      // FFN1 acts (tf32-rounded)
__device__ float g_y[(size_t)MAXROWS * D_MODEL];     // FFN2 outputs (fp32)
__device__ float g_xr[(size_t)T_TOK * D_MODEL];      // x, tf32-rounded, token order
__device__ float g_w1t[(size_t)NE * D_FF * D_MODEL]; // W1^T [E][F][D] (k-major, rounded)
__device__ float g_w2t[(size_t)NE * D_MODEL * D_FF]; // W2^T [E][D][F] (k-major, rounded)
__device__ int   g_rowtok[MAXROWS];
__device__ int   g_tileE[MAXTILES];
__device__ int   g_tokE[T_TOK * 2];
__device__ float g_tokW[T_TOK * 2];
__device__ int   g_loc[T_TOK * 2];

// ---------------- helpers ----------------------------------------------------
__device__ __forceinline__ unsigned f2tf(float f) {
    unsigned u;
    asm("cvt.rna.tf32.f32 %0, %1;" : "=r"(u) : "f"(f));
    return u;
}
__device__ __forceinline__ uint32_t smem_u32(const void* p) {
    uint32_t a;
    asm("{ .reg .u64 t; cvta.to.shared.u64 t, %1; cvt.u32.u64 %0, t; }" : "=r"(a) : "l"(p));
    return a;
}
#define CP_ASYNC16(dst, src) \
    asm volatile("cp.async.cg.shared.global [%0], [%1], 16;" :: "r"(dst), "l"(src) : "memory")
#define CP_ASYNC16Z(dst, src, sz) \
    asm volatile("cp.async.cg.shared.global [%0], [%1], 16, %2;" :: "r"(dst), "l"(src), "r"(sz) : "memory")
#define CP_COMMIT() asm volatile("cp.async.commit_group;" ::: "memory")
#define CP_WAIT1()  asm volatile("cp.async.wait_group 1;" ::: "memory")
#define LDSM4(r, a)                                                               \
    asm volatile("ldmatrix.sync.aligned.m8n8.x4.shared.b16 {%0,%1,%2,%3}, [%4];" \
        : "=r"((r)[0]), "=r"((r)[1]), "=r"((r)[2]), "=r"((r)[3]) : "r"(a))

__device__ __forceinline__ void mma8(float (&d)[4], const unsigned (&a)[4],
                                     unsigned b0, unsigned b1) {
    asm volatile(
        "mma.sync.aligned.m16n8k8.row.col.f32.tf32.tf32.f32 "
        "{%0,%1,%2,%3}, {%4,%5,%6,%7}, {%8,%9}, {%0,%1,%2,%3};\n"
        : "+f"(d[0]), "+f"(d[1]), "+f"(d[2]), "+f"(d[3])
        : "r"(a[0]), "r"(a[1]), "r"(a[2]), "r"(a[3]), "r"(b0), "r"(b1));
}

__device__ __forceinline__ float act_gelu(float h) {
    return 0.5f * h * (1.0f + erff(h * 0.70710678118654752f));
}
__device__ __forceinline__ float act_silu(float h) {
    return h / (1.0f + __expf(-h));
}

// ---------------- launch 0: transpose + tf32-round BOTH weights ---------------
// z = w*8 + e. Output k-major: w1t [E][F][D], w2t [E][D][F].
__global__ void tp_kernel(const float* __restrict__ W1,
                          const float* __restrict__ W2) {
    __shared__ float s[32][33];
    int z = blockIdx.z, w = z >> 3, e = z & 7;
    const float* Ws = w ? W2 : W1;
    float* Wd = w ? g_w2t : g_w1t;
    int R = w ? D_FF : D_MODEL;     // source rows (k dim of output)
    int C = w ? D_MODEL : D_FF;     // source cols (n dim of output)
    int cx = w ? blockIdx.y : blockIdx.x;   // C/32 range
    int ry = w ? blockIdx.x : blockIdx.y;   // R/32 range
    int c0 = cx * 32, r0 = ry * 32;
    int tx = threadIdx.x, ty = threadIdx.y;
    const float* Wb = Ws + (size_t)e * R * C;
    float* Wtb = Wd + (size_t)e * R * C;
#pragma unroll
    for (int j = 0; j < 4; j++)
        s[ty + 8 * j][tx] = Wb[(size_t)(r0 + ty + 8 * j) * C + c0 + tx];
    __syncthreads();
#pragma unroll
    for (int j = 0; j < 4; j++)
        Wtb[(size_t)(c0 + ty + 8 * j) * R + r0 + tx] =
            __uint_as_float(f2tf(s[tx][ty + 8 * j]));
}

// ---------------- launch 1: gate (fp32 exact) + tf32-round x -------------------
__global__ void gate_kernel(const float* __restrict__ x,
                            const float* __restrict__ Wg,
                            const float* __restrict__ bg) {
    int tid = threadIdx.x, wid = tid >> 5, lane = tid & 31;
    int t = blockIdx.x * 8 + wid;
    const float* xr = x + (size_t)t * D_MODEL;
    float acc[8] = {0, 0, 0, 0, 0, 0, 0, 0};
    for (int d = lane; d < D_MODEL; d += 32) {
        float xv = xr[d];
        const float4* w = (const float4*)(Wg + d * 8);
        float4 w0 = w[0], w1 = w[1];
        acc[0] += xv * w0.x; acc[1] += xv * w0.y;
        acc[2] += xv * w0.z; acc[3] += xv * w0.w;
        acc[4] += xv * w1.x; acc[5] += xv * w1.y;
        acc[6] += xv * w1.z; acc[7] += xv * w1.w;
    }
#pragma unroll
    for (int o = 16; o > 0; o >>= 1)
#pragma unroll
        for (int e = 0; e < 8; e++)
            acc[e] += __shfl_xor_sync(0xffffffffu, acc[e], o);
    if (lane == 0) {
        float v0 = -1e30f, v1 = -1e30f;
        int i0 = 0, i1 = 0;
#pragma unroll
        for (int e = 0; e < 8; e++) {
            float v = acc[e] + bg[e];
            if (v > v0) { v1 = v0; i1 = i0; v0 = v; i0 = e; }
            else if (v > v1) { v1 = v; i1 = e; }
        }
        float e1 = expf(v1 - v0);
        float inv = 1.0f / (1.0f + e1);
        g_tokE[t * 2]     = i0; g_tokW[t * 2]     = inv;
        g_tokE[t * 2 + 1] = i1; g_tokW[t * 2 + 1] = e1 * inv;
    }
    // round-copy this block's 8 tokens of x -> g_xr
    size_t base = (size_t)blockIdx.x * 8 * (D_MODEL / 4);
    const float4* xs = (const float4*)x + base;
    float4* xd = (float4*)g_xr + base;
#pragma unroll
    for (int i = 0; i < 8; i++) {
        float4 v = xs[tid + i * 256];
        v.x = __uint_as_float(f2tf(v.x));
        v.y = __uint_as_float(f2tf(v.y));
        v.z = __uint_as_float(f2tf(v.z));
        v.w = __uint_as_float(f2tf(v.w));
        xd[tid + i * 256] = v;
    }
}

// ---------------- launch 2: route (histogram + plan + scatter, 1 block) --------
__global__ void route_kernel() {
    __shared__ int sc[NE], scur[NE];
    int tid = threadIdx.x;
    if (tid < NE) sc[tid] = 0;
    for (int r = tid; r < MAXROWS; r += 1024) g_rowtok[r] = -1;
    __syncthreads();
    for (int i = tid; i < T_TOK * 2; i += 1024) atomicAdd(&sc[g_tokE[i]], 1);
    __syncthreads();
    if (tid == 0) {
        int ofs = 0;
        for (int e = 0; e < NE; e++) {
            scur[e] = ofs;
            int ntl = (sc[e] + 127) >> 7;
            int t0 = ofs >> 7;
            for (int j = 0; j < ntl; j++) g_tileE[t0 + j] = e;
            ofs += ntl << 7;
        }
        for (int t = ofs >> 7; t < MAXTILES; t++) g_tileE[t] = -1;
    }
    __syncthreads();
    for (int i = tid; i < T_TOK * 2; i += 1024) {
        int e = g_tokE[i];
        int row = atomicAdd(&scur[e], 1);
        g_loc[i] = row;
        g_rowtok[row] = i >> 1;
    }
}

// ---------------- launches 3/4: TF32 GEMM, ldmatrix + cp.async pipeline --------
// A smem [128][36] words (m-major), B smem [256][36] words (k-major).
// Both fragment loads via ldmatrix.x4 (tf32-as-4xb16 trick), padded stride 9x16B
// -> conflict-free. FFN1 gathers A rows through g_rowtok with cp.async zfill.
template <int KTOT, int NTOT, bool FFN1_>
__global__ __launch_bounds__(256, 1) void ffn_mma(const float* __restrict__ bias) {
    constexpr int NT = NTOT / 256;
    constexpr int NC = KTOT / 32;

    int bid = blockIdx.x;
    int gid = bid / (8 * NT), rem = bid % (8 * NT);
    int mt = gid * 8 + (rem & 7);
    int nt = rem >> 3;
    int e = g_tileE[mt];
    if (e < 0) return;

    extern __shared__ unsigned smv[];
    uint32_t sb = smem_u32(smv);

    int tid = threadIdx.x, lane = tid & 31, wid = tid >> 5;
    int wm = wid >> 2, wn = wid & 3;
    int lr = lane >> 2, lc = lane & 3;
    int m0 = mt * 128, n0 = nt * 256;

    const float* Bt = FFN1_ ? g_w1t : g_w2t;
    const float* Bb = Bt + (size_t)e * D_MODEL * D_FF + (size_t)n0 * KTOT;
    float* Out = FFN1_ ? g_act : g_y;

    // ---- producer addressing: granule (16B) mappings ----
    int rA = tid >> 3, qA = tid & 7;
    const float* srcA[4];
    unsigned szA[4];
    uint32_t dA[4];
#pragma unroll
    for (int t = 0; t < 4; t++) {
        int r = rA + 32 * t;
        dA[t] = (uint32_t)(r * 144 + qA * 16);
        if (FFN1_) {
            int tok = g_rowtok[m0 + r];
            szA[t] = tok >= 0 ? 16u : 0u;
            srcA[t] = g_xr + (size_t)(tok >= 0 ? tok : 0) * KTOT + qA * 4;
        } else {
            szA[t] = 16u;
            srcA[t] = g_act + (size_t)(m0 + r) * KTOT + qA * 4;
        }
    }
    const float* srcB[8];
    uint32_t dB[8];
#pragma unroll
    for (int t = 0; t < 8; t++) {
        int r = rA + 32 * t;
        dB[t] = (uint32_t)(AB + r * 144 + qA * 16);
        srcB[t] = Bb + (size_t)r * KTOT + qA * 4;
    }

    auto issue = [&](int c) {
        if (c >= NC) return;
        uint32_t s0 = sb + (uint32_t)(c % NSTAGE) * STAGE_BYTES;
        int k0 = c * 32;
#pragma unroll
        for (int t = 0; t < 4; t++) CP_ASYNC16Z(s0 + dA[t], srcA[t] + k0, szA[t]);
#pragma unroll
        for (int t = 0; t < 8; t++) CP_ASYNC16(s0 + dB[t], srcB[t] + k0);
    };

    // ---- consumer ldmatrix addressing (per-lane invariants) ----
    int aRow = wm * 64 + ((lane >> 3) & 1) * 8 + (lane & 7);
    uint32_t aOff = (uint32_t)(aRow * 36 + ((lane >> 4) & 1) * 4) * 4;
    int bRow = wn * 64 + ((lane >> 4) & 1) * 8 + (lane & 7);
    uint32_t bOff = (uint32_t)AB + (uint32_t)(bRow * 36 + ((lane >> 3) & 1) * 4) * 4;

    float acc[4][8][4];
#pragma unroll
    for (int i = 0; i < 4; i++)
#pragma unroll
        for (int j = 0; j < 8; j++)
#pragma unroll
            for (int k = 0; k < 4; k++) acc[i][j][k] = 0.0f;

    unsigned fa[2][4][4], fb[2][4][4];

    issue(0); CP_COMMIT();
    issue(1); CP_COMMIT();

    for (int c = 0; c < NC; c++) {
        CP_WAIT1();
        __syncthreads();
        issue(c + 2);
        CP_COMMIT();

        uint32_t sA = sb + (uint32_t)(c % NSTAGE) * STAGE_BYTES + aOff;
        uint32_t sB = sb + (uint32_t)(c % NSTAGE) * STAGE_BYTES + bOff;
        // preload ks=0 fragments
#pragma unroll
        for (int mf = 0; mf < 4; mf++) LDSM4(fa[0][mf], sA + mf * 2304);
#pragma unroll
        for (int p = 0; p < 4; p++)  LDSM4(fb[0][p], sB + p * 2304);
#pragma unroll
        for (int ks = 0; ks < 4; ks++) {
            int cur = ks & 1, nxt = cur ^ 1;
            if (ks < 3) {
                uint32_t kadd = (uint32_t)(ks + 1) * 32;
#pragma unroll
                for (int mf = 0; mf < 4; mf++) LDSM4(fa[nxt][mf], sA + mf * 2304 + kadd);
#pragma unroll
                for (int p = 0; p < 4; p++)  LDSM4(fb[nxt][p], sB + p * 2304 + kadd);
            }
#pragma unroll
            for (int nf = 0; nf < 8; nf++) {
                unsigned b0 = fb[cur][nf >> 1][(nf & 1) * 2];
                unsigned b1 = fb[cur][nf >> 1][(nf & 1) * 2 + 1];
#pragma unroll
                for (int mf = 0; mf < 4; mf++)
                    mma8(acc[mf][nf], fa[cur][mf], b0, b1);
            }
        }
        __syncthreads();
    }

    // ---- epilogue: bias + activation (+tf32 re-round for FFN1) ----
    bool isGelu = !(e & 1);
    const float* bb = bias + (size_t)e * NTOT + n0;
#pragma unroll
    for (int mf = 0; mf < 4; mf++) {
#pragma unroll
        for (int nf = 0; nf < 8; nf++) {
            int row = m0 + wm * 64 + mf * 16 + lr;
            int colL = wn * 64 + nf * 8 + 2 * lc;
            float b0v = bb[colL], b1v = bb[colL + 1];
            float v00 = acc[mf][nf][0] + b0v;
            float v01 = acc[mf][nf][1] + b1v;
            float v10 = acc[mf][nf][2] + b0v;
            float v11 = acc[mf][nf][3] + b1v;
            if (FFN1_) {
                if (isGelu) {
                    v00 = act_gelu(v00); v01 = act_gelu(v01);
                    v10 = act_gelu(v10); v11 = act_gelu(v11);
                } else {
                    v00 = act_silu(v00); v01 = act_silu(v01);
                    v10 = act_silu(v10); v11 = act_silu(v11);
                }
                v00 = __uint_as_float(f2tf(v00));
                v01 = __uint_as_float(f2tf(v01));
                v10 = __uint_as_float(f2tf(v10));
                v11 = __uint_as_float(f2tf(v11));
            }
            float* op = Out + (size_t)row * NTOT + n0 + colL;
            *(float2*)op = make_float2(v00, v01);
            *(float2*)(op + (size_t)8 * NTOT) = make_float2(v10, v11);
        }
    }
}

// ---------------- launch 5: combine --------------------------------------------
__global__ void combine_kernel(float* __restrict__ out) {
    int t = blockIdx.x, c = threadIdx.x;
    float w0 = g_tokW[t * 2], w1 = g_tokW[t * 2 + 1];
    int l0 = g_loc[t * 2], l1 = g_loc[t * 2 + 1];
    const float4 y0 = *(const float4*)(g_y + (size_t)l0 * D_MODEL + c * 4);
    const float4 y1 = *(const float4*)(g_y + (size_t)l1 * D_MODEL + c * 4);
    float4 o;
    o.x = w0 * y0.x + w1 * y1.x;
    o.y = w0 * y0.y + w1 * y1.y;
    o.z = w0 * y0.z + w1 * y1.z;
    o.w = w0 * y0.w + w1 * y1.w;
    *(float4*)(out + (size_t)t * D_MODEL + c * 4) = o;
}

// ---------------- host launcher -------------------------------------------------
extern "C" void kernel_launch(void* const* d_in, const int* in_sizes, int n_in,
                              void* d_out, int out_size) {
    const float* x  = (const float*)d_in[0];
    const float* W1 = (const float*)d_in[1];
    const float* b1 = (const float*)d_in[2];
    const float* W2 = (const float*)d_in[3];
    const float* b2 = (const float*)d_in[4];
    const float* Wg = (const float*)d_in[5];
    const float* bg = (const float*)d_in[6];
    float* out = (float*)d_out;

    cudaFuncSetAttribute(ffn_mma<D_MODEL, D_FF, true>,
                         cudaFuncAttributeMaxDynamicSharedMemorySize, SMEM_TOTAL);
    cudaFuncSetAttribute(ffn_mma<D_FF, D_MODEL, false>,
                         cudaFuncAttributeMaxDynamicSharedMemorySize, SMEM_TOTAL);

    tp_kernel<<<dim3(128, 32, 16), dim3(32, 8)>>>(W1, W2);       // 0
    gate_kernel<<<T_TOK / 8, 256>>>(x, Wg, bg);                  // 1
    route_kernel<<<1, 1024>>>();                                 // 2
    ffn_mma<D_MODEL, D_FF, true>                                 // 3
        <<<MAXTILES * (D_FF / 256), 256, SMEM_TOTAL>>>(b1);
    ffn_mma<D_FF, D_MODEL, false>                                // 4
        <<<MAXTILES * (D_MODEL / 256), 256, SMEM_TOTAL>>>(b2);
    combine_kernel<<<T_TOK, 256>>>(out);                         // 5
}

// round 8
// speedup vs baseline: 1.0412x; 1.0412x over previous
#include <cuda_runtime.h>
#include <math.h>
#include <stdint.h>

#define D_MODEL 1024
#define D_FF    4096
#define NE      8
#define T_TOK   4096
#define MAXROWS 9216      // 8192 rows + 8 experts * 128-pad
#define MAXTILES 72

// GEMM tiling: CTA 128(M) x 256(N) x 32(K), 512 thr, warps 2x8 of 64x32
#define NSTAGE 3
#define AW     4608                 // A stage words: 128 rows * 36
#define BW     9216                 // B stage words: 256 rows * 36 (k-major)
#define AB     (AW * 4)             // 18432 B
#define STAGE_BYTES ((AW + BW) * 4) // 55296 B
#define SMEM_TOTAL (NSTAGE * STAGE_BYTES)  // 165888 B

// ---------------- scratch (static device memory: allocation-free) -------------
__device__ float g_act[(size_t)MAXROWS * D_FF];      // FFN1 acts (tf32-rounded)
__device__ float g_y[(size_t)MAXROWS * D_MODEL];     // FFN2 outputs (fp32)
__device__ float g_xr[(size_t)T_TOK * D_MODEL];      // x, tf32-rounded, token order
__device__ float g_w1t[(size_t)NE * D_FF * D_MODEL]; // W1^T [E][F][D] (k-major, rounded)
__device__ float g_w2t[(size_t)NE * D_MODEL * D_FF]; // W2^T [E][D][F] (k-major, rounded)
__device__ int   g_rowtok[MAXROWS];
__device__ int   g_tileE[MAXTILES];
__device__ int   g_tokE[T_TOK * 2];
__device__ float g_tokW[T_TOK * 2];
__device__ int   g_loc[T_TOK * 2];

// ---------------- helpers ----------------------------------------------------
__device__ __forceinline__ unsigned f2tf(float f) {
    unsigned u;
    asm("cvt.rna.tf32.f32 %0, %1;" : "=r"(u) : "f"(f));
    return u;
}
__device__ __forceinline__ uint32_t smem_u32(const void* p) {
    uint32_t a;
    asm("{ .reg .u64 t; cvta.to.shared.u64 t, %1; cvt.u32.u64 %0, t; }" : "=r"(a) : "l"(p));
    return a;
}
#define CP_ASYNC16(dst, src) \
    asm volatile("cp.async.cg.shared.global [%0], [%1], 16;" :: "r"(dst), "l"(src) : "memory")
#define CP_ASYNC16Z(dst, src, sz) \
    asm volatile("cp.async.cg.shared.global [%0], [%1], 16, %2;" :: "r"(dst), "l"(src), "r"(sz) : "memory")
#define CP_COMMIT() asm volatile("cp.async.commit_group;" ::: "memory")
#define CP_WAIT1()  asm volatile("cp.async.wait_group 1;" ::: "memory")
#define LDSM4(r, a)                                                               \
    asm volatile("ldmatrix.sync.aligned.m8n8.x4.shared.b16 {%0,%1,%2,%3}, [%4];" \
        : "=r"((r)[0]), "=r"((r)[1]), "=r"((r)[2]), "=r"((r)[3]) : "r"(a))

__device__ __forceinline__ void mma8(float (&d)[4], const unsigned (&a)[4],
                                     unsigned b0, unsigned b1) {
    asm volatile(
        "mma.sync.aligned.m16n8k8.row.col.f32.tf32.tf32.f32 "
        "{%0,%1,%2,%3}, {%4,%5,%6,%7}, {%8,%9}, {%0,%1,%2,%3};\n"
        : "+f"(d[0]), "+f"(d[1]), "+f"(d[2]), "+f"(d[3])
        : "r"(a[0]), "r"(a[1]), "r"(a[2]), "r"(a[3]), "r"(b0), "r"(b1));
}

__device__ __forceinline__ float act_gelu(float h) {
    return 0.5f * h * (1.0f + erff(h * 0.70710678118654752f));
}
__device__ __forceinline__ float act_silu(float h) {
    return h / (1.0f + __expf(-h));
}

// ---------------- launch 0: transpose + tf32-round BOTH weights ---------------
__global__ void tp_kernel(const float* __restrict__ W1,
                          const float* __restrict__ W2) {
    __shared__ float s[32][33];
    int z = blockIdx.z, w = z >> 3, e = z & 7;
    const float* Ws = w ? W2 : W1;
    float* Wd = w ? g_w2t : g_w1t;
    int R = w ? D_FF : D_MODEL;
    int C = w ? D_MODEL : D_FF;
    int cx = w ? blockIdx.y : blockIdx.x;
    int ry = w ? blockIdx.x : blockIdx.y;
    int c0 = cx * 32, r0 = ry * 32;
    int tx = threadIdx.x, ty = threadIdx.y;
    const float* Wb = Ws + (size_t)e * R * C;
    float* Wtb = Wd + (size_t)e * R * C;
#pragma unroll
    for (int j = 0; j < 4; j++)
        s[ty + 8 * j][tx] = Wb[(size_t)(r0 + ty + 8 * j) * C + c0 + tx];
    __syncthreads();
#pragma unroll
    for (int j = 0; j < 4; j++)
        Wtb[(size_t)(c0 + ty + 8 * j) * R + r0 + tx] =
            __uint_as_float(f2tf(s[tx][ty + 8 * j]));
}

// ---------------- launch 1: gate (fp32 exact) + tf32-round x -------------------
__global__ void gate_kernel(const float* __restrict__ x,
                            const float* __restrict__ Wg,
                            const float* __restrict__ bg) {
    int tid = threadIdx.x, wid = tid >> 5, lane = tid & 31;
    int t = blockIdx.x * 8 + wid;
    const float* xr = x + (size_t)t * D_MODEL;
    float acc[8] = {0, 0, 0, 0, 0, 0, 0, 0};
    for (int d = lane; d < D_MODEL; d += 32) {
        float xv = xr[d];
        const float4* w = (const float4*)(Wg + d * 8);
        float4 w0 = w[0], w1 = w[1];
        acc[0] += xv * w0.x; acc[1] += xv * w0.y;
        acc[2] += xv * w0.z; acc[3] += xv * w0.w;
        acc[4] += xv * w1.x; acc[5] += xv * w1.y;
        acc[6] += xv * w1.z; acc[7] += xv * w1.w;
    }
#pragma unroll
    for (int o = 16; o > 0; o >>= 1)
#pragma unroll
        for (int e = 0; e < 8; e++)
            acc[e] += __shfl_xor_sync(0xffffffffu, acc[e], o);
    if (lane == 0) {
        float v0 = -1e30f, v1 = -1e30f;
        int i0 = 0, i1 = 0;
#pragma unroll
        for (int e = 0; e < 8; e++) {
            float v = acc[e] + bg[e];
            if (v > v0) { v1 = v0; i1 = i0; v0 = v; i0 = e; }
            else if (v > v1) { v1 = v; i1 = e; }
        }
        float e1 = expf(v1 - v0);
        float inv = 1.0f / (1.0f + e1);
        g_tokE[t * 2]     = i0; g_tokW[t * 2]     = inv;
        g_tokE[t * 2 + 1] = i1; g_tokW[t * 2 + 1] = e1 * inv;
    }
    size_t base = (size_t)blockIdx.x * 8 * (D_MODEL / 4);
    const float4* xs = (const float4*)x + base;
    float4* xd = (float4*)g_xr + base;
#pragma unroll
    for (int i = 0; i < 8; i++) {
        float4 v = xs[tid + i * 256];
        v.x = __uint_as_float(f2tf(v.x));
        v.y = __uint_as_float(f2tf(v.y));
        v.z = __uint_as_float(f2tf(v.z));
        v.w = __uint_as_float(f2tf(v.w));
        xd[tid + i * 256] = v;
    }
}

// ---------------- launch 2: route (histogram + plan + scatter, 1 block) --------
__global__ void route_kernel() {
    __shared__ int sc[NE], scur[NE];
    int tid = threadIdx.x;
    if (tid < NE) sc[tid] = 0;
    for (int r = tid; r < MAXROWS; r += 1024) g_rowtok[r] = -1;
    __syncthreads();
    for (int i = tid; i < T_TOK * 2; i += 1024) atomicAdd(&sc[g_tokE[i]], 1);
    __syncthreads();
    if (tid == 0) {
        int ofs = 0;
        for (int e = 0; e < NE; e++) {
            scur[e] = ofs;
            int ntl = (sc[e] + 127) >> 7;
            int t0 = ofs >> 7;
            for (int j = 0; j < ntl; j++) g_tileE[t0 + j] = e;
            ofs += ntl << 7;
        }
        for (int t = ofs >> 7; t < MAXTILES; t++) g_tileE[t] = -1;
    }
    __syncthreads();
    for (int i = tid; i < T_TOK * 2; i += 1024) {
        int e = g_tokE[i];
        int row = atomicAdd(&scur[e], 1);
        g_loc[i] = row;
        g_rowtok[row] = i >> 1;
    }
}

// ---------------- launches 3/4: TF32 GEMM, 512 thr, 16 warps of 64x32 ----------
// A smem [128][36] words (m-major), B smem [256][36] words (k-major).
// ldmatrix.x4 both operands (tf32-as-b16 trick); fa single-buffered (16 reg),
// fb double-buffered; acc 64 reg -> fits 128 regs => 16 warps = 4/SMSP.
template <int KTOT, int NTOT, bool FFN1_>
__global__ __launch_bounds__(512, 1) void ffn_mma(const float* __restrict__ bias) {
    constexpr int NT = NTOT / 256;
    constexpr int NC = KTOT / 32;

    int bid = blockIdx.x;
    int gid = bid / (8 * NT), rem = bid % (8 * NT);
    int mt = gid * 8 + (rem & 7);
    int nt = rem >> 3;
    int e = g_tileE[mt];
    if (e < 0) return;

    extern __shared__ unsigned smv[];
    uint32_t sb = smem_u32(smv);

    int tid = threadIdx.x, lane = tid & 31, wid = tid >> 5;
    int wm = wid >> 3, wn = wid & 7;     // 2 x 8 warp grid, warp tile 64x32
    int lr = lane >> 2, lc = lane & 3;
    int m0 = mt * 128, n0 = nt * 256;

    const float* Bt = FFN1_ ? g_w1t : g_w2t;
    const float* Bb = Bt + (size_t)e * D_MODEL * D_FF + (size_t)n0 * KTOT;
    float* Out = FFN1_ ? g_act : g_y;

    // ---- producer: A 1024 granules -> 2/thread, B 2048 granules -> 4/thread ----
    int rA = tid >> 3, qA = tid & 7;      // rA 0..63
    const float* srcA[2];
    unsigned szA[2];
    uint32_t dA[2];
#pragma unroll
    for (int t = 0; t < 2; t++) {
        int r = rA + 64 * t;
        dA[t] = (uint32_t)(r * 144 + qA * 16);
        if (FFN1_) {
            int tok = g_rowtok[m0 + r];
            szA[t] = tok >= 0 ? 16u : 0u;
            srcA[t] = g_xr + (size_t)(tok >= 0 ? tok : 0) * KTOT + qA * 4;
        } else {
            szA[t] = 16u;
            srcA[t] = g_act + (size_t)(m0 + r) * KTOT + qA * 4;
        }
    }
    const float* srcB0 = Bb + (size_t)rA * KTOT + qA * 4;  // rows rA + 64*t
    uint32_t dB0 = (uint32_t)(AB + rA * 144 + qA * 16);

    auto issue = [&](int c) {
        if (c >= NC) return;
        uint32_t s0 = sb + (uint32_t)(c % NSTAGE) * STAGE_BYTES;
        int k0 = c * 32;
#pragma unroll
        for (int t = 0; t < 2; t++) CP_ASYNC16Z(s0 + dA[t], srcA[t] + k0, szA[t]);
        const float* bp = srcB0 + k0;
#pragma unroll
        for (int t = 0; t < 4; t++)
            CP_ASYNC16(s0 + dB0 + (uint32_t)t * 9216, bp + (size_t)t * 64 * KTOT);
    };

    // ---- consumer ldmatrix addressing ----
    int aRow = wm * 64 + ((lane >> 3) & 1) * 8 + (lane & 7);
    uint32_t aOff = (uint32_t)(aRow * 36 + ((lane >> 4) & 1) * 4) * 4;
    int bRow = wn * 32 + ((lane >> 4) & 1) * 8 + (lane & 7);
    uint32_t bOff = (uint32_t)AB + (uint32_t)(bRow * 36 + ((lane >> 3) & 1) * 4) * 4;

    float acc[4][4][4];
#pragma unroll
    for (int i = 0; i < 4; i++)
#pragma unroll
        for (int j = 0; j < 4; j++)
#pragma unroll
            for (int k = 0; k < 4; k++) acc[i][j][k] = 0.0f;

    unsigned fa[4][4], fb[2][2][4];

    issue(0); CP_COMMIT();
    issue(1); CP_COMMIT();

    for (int c = 0; c < NC; c++) {
        CP_WAIT1();
        __syncthreads();
        issue(c + 2);
        CP_COMMIT();

        uint32_t st = sb + (uint32_t)(c % NSTAGE) * STAGE_BYTES;
        uint32_t sA = st + aOff;
        uint32_t sB = st + bOff;
        LDSM4(fb[0][0], sB);
        LDSM4(fb[0][1], sB + 2304);
#pragma unroll
        for (int ks = 0; ks < 4; ks++) {
            int cur = ks & 1, nxt = cur ^ 1;
#pragma unroll
            for (int mf = 0; mf < 4; mf++)
                LDSM4(fa[mf], sA + mf * 2304 + ks * 32);
            if (ks < 3) {
                LDSM4(fb[nxt][0], sB + (ks + 1) * 32);
                LDSM4(fb[nxt][1], sB + 2304 + (ks + 1) * 32);
            }
#pragma unroll
            for (int nf = 0; nf < 4; nf++) {
                unsigned b0 = fb[cur][nf >> 1][(nf & 1) * 2];
                unsigned b1 = fb[cur][nf >> 1][(nf & 1) * 2 + 1];
#pragma unroll
                for (int mf = 0; mf < 4; mf++)
                    mma8(acc[mf][nf], fa[mf], b0, b1);
            }
        }
    }

    // ---- epilogue: bias + activation (+tf32 re-round for FFN1) ----
    bool isGelu = !(e & 1);
    const float* bb = bias + (size_t)e * NTOT + n0;
#pragma unroll
    for (int mf = 0; mf < 4; mf++) {
#pragma unroll
        for (int nf = 0; nf < 4; nf++) {
            int row = m0 + wm * 64 + mf * 16 + lr;
            int colL = wn * 32 + nf * 8 + 2 * lc;
            float b0v = bb[colL], b1v = bb[colL + 1];
            float v00 = acc[mf][nf][0] + b0v;
            float v01 = acc[mf][nf][1] + b1v;
            float v10 = acc[mf][nf][2] + b0v;
            float v11 = acc[mf][nf][3] + b1v;
            if (FFN1_) {
                if (isGelu) {
                    v00 = act_gelu(v00); v01 = act_gelu(v01);
                    v10 = act_gelu(v10); v11 = act_gelu(v11);
                } else {
                    v00 = act_silu(v00); v01 = act_silu(v01);
                    v10 = act_silu(v10); v11 = act_silu(v11);
                }
                v00 = __uint_as_float(f2tf(v00));
                v01 = __uint_as_float(f2tf(v01));
                v10 = __uint_as_float(f2tf(v10));
                v11 = __uint_as_float(f2tf(v11));
            }
            float* op = Out + (size_t)row * NTOT + n0 + colL;
            *(float2*)op = make_float2(v00, v01);
            *(float2*)(op + (size_t)8 * NTOT) = make_float2(v10, v11);
        }
    }
}

// ---------------- launch 5: combine --------------------------------------------
__global__ void combine_kernel(float* __restrict__ out) {
    int t = blockIdx.x, c = threadIdx.x;
    float w0 = g_tokW[t * 2], w1 = g_tokW[t * 2 + 1];
    int l0 = g_loc[t * 2], l1 = g_loc[t * 2 + 1];
    const float4 y0 = *(const float4*)(g_y + (size_t)l0 * D_MODEL + c * 4);
    const float4 y1 = *(const float4*)(g_y + (size_t)l1 * D_MODEL + c * 4);
    float4 o;
    o.x = w0 * y0.x + w1 * y1.x;
    o.y = w0 * y0.y + w1 * y1.y;
    o.z = w0 * y0.z + w1 * y1.z;
    o.w = w0 * y0.w + w1 * y1.w;
    *(float4*)(out + (size_t)t * D_MODEL + c * 4) = o;
}

// ---------------- host launcher -------------------------------------------------
extern "C" void kernel_launch(void* const* d_in, const int* in_sizes, int n_in,
                              void* d_out, int out_size) {
    const float* x  = (const float*)d_in[0];
    const float* W1 = (const float*)d_in[1];
    const float* b1 = (const float*)d_in[2];
    const float* W2 = (const float*)d_in[3];
    const float* b2 = (const float*)d_in[4];
    const float* Wg = (const float*)d_in[5];
    const float* bg = (const float*)d_in[6];
    float* out = (float*)d_out;

    cudaFuncSetAttribute(ffn_mma<D_MODEL, D_FF, true>,
                         cudaFuncAttributeMaxDynamicSharedMemorySize, SMEM_TOTAL);
    cudaFuncSetAttribute(ffn_mma<D_FF, D_MODEL, false>,
                         cudaFuncAttributeMaxDynamicSharedMemorySize, SMEM_TOTAL);

    tp_kernel<<<dim3(128, 32, 16), dim3(32, 8)>>>(W1, W2);       // 0
    gate_kernel<<<T_TOK / 8, 256>>>(x, Wg, bg);                  // 1
    route_kernel<<<1, 1024>>>();                                 // 2
    ffn_mma<D_MODEL, D_FF, true>                                 // 3
        <<<MAXTILES * (D_FF / 256), 512, SMEM_TOTAL>>>(b1);
    ffn_mma<D_FF, D_MODEL, false>                                // 4
        <<<MAXTILES * (D_MODEL / 256), 512, SMEM_TOTAL>>>(b2);
    combine_kernel<<<T_TOK, 256>>>(out);                         // 5
}

// round 9
// speedup vs baseline: 1.1097x; 1.0657x over previous
#include <cuda_runtime.h>
#include <math.h>
#include <stdint.h>

#define D_MODEL 1024
#define D_FF    4096
#define NE      8
#define T_TOK   4096
#define MAXROWS 9216      // 8192 rows + 8 experts * 128-pad
#define MAXTILES 72

// GEMM tiling: CTA 128(M) x 128(N) x 32(K), 128 thr, 4 warps (2x2) of 64x64.
// 3-stage cp.async; smem 108KB/CTA -> 2 CTAs/SM for cross-CTA overlap.
#define NSTAGE 3
#define AW     4608                 // A stage words: 128 rows * 36
#define BWRD   4608                 // B stage words: 128 rows * 36 (k-major)
#define AB     (AW * 4)             // 18432 B
#define STAGE_BYTES ((AW + BWRD) * 4)      // 36864 B
#define SMEM_TOTAL (NSTAGE * STAGE_BYTES)  // 110592 B

// ---------------- scratch (static device memory: allocation-free) -------------
__device__ float g_act[(size_t)MAXROWS * D_FF];      // FFN1 acts (tf32-rounded)
__device__ float g_y[(size_t)MAXROWS * D_MODEL];     // FFN2 outputs (fp32)
__device__ float g_xr[(size_t)T_TOK * D_MODEL];      // x, tf32-rounded, token order
__device__ float g_w1t[(size_t)NE * D_FF * D_MODEL]; // W1^T [E][F][D] (k-major, rounded)
__device__ float g_w2t[(size_t)NE * D_MODEL * D_FF]; // W2^T [E][D][F] (k-major, rounded)
__device__ int   g_rowtok[MAXROWS];
__device__ int   g_tileE[MAXTILES];
__device__ int   g_tokE[T_TOK * 2];
__device__ float g_tokW[T_TOK * 2];
__device__ int   g_loc[T_TOK * 2];

// ---------------- helpers ----------------------------------------------------
__device__ __forceinline__ unsigned f2tf(float f) {
    unsigned u;
    asm("cvt.rna.tf32.f32 %0, %1;" : "=r"(u) : "f"(f));
    return u;
}
__device__ __forceinline__ uint32_t smem_u32(const void* p) {
    uint32_t a;
    asm("{ .reg .u64 t; cvta.to.shared.u64 t, %1; cvt.u32.u64 %0, t; }" : "=r"(a) : "l"(p));
    return a;
}
#define CP_ASYNC16(dst, src) \
    asm volatile("cp.async.cg.shared.global [%0], [%1], 16;" :: "r"(dst), "l"(src) : "memory")
#define CP_ASYNC16Z(dst, src, sz) \
    asm volatile("cp.async.cg.shared.global [%0], [%1], 16, %2;" :: "r"(dst), "l"(src), "r"(sz) : "memory")
#define CP_COMMIT() asm volatile("cp.async.commit_group;" ::: "memory")
#define CP_WAIT1()  asm volatile("cp.async.wait_group 1;" ::: "memory")
#define LDSM4(r, a)                                                               \
    asm volatile("ldmatrix.sync.aligned.m8n8.x4.shared.b16 {%0,%1,%2,%3}, [%4];" \
        : "=r"((r)[0]), "=r"((r)[1]), "=r"((r)[2]), "=r"((r)[3]) : "r"(a))

__device__ __forceinline__ void mma8(float (&d)[4], const unsigned (&a)[4],
                                     unsigned b0, unsigned b1) {
    asm volatile(
        "mma.sync.aligned.m16n8k8.row.col.f32.tf32.tf32.f32 "
        "{%0,%1,%2,%3}, {%4,%5,%6,%7}, {%8,%9}, {%0,%1,%2,%3};\n"
        : "+f"(d[0]), "+f"(d[1]), "+f"(d[2]), "+f"(d[3])
        : "r"(a[0]), "r"(a[1]), "r"(a[2]), "r"(a[3]), "r"(b0), "r"(b1));
}

__device__ __forceinline__ float act_gelu(float h) {
    return 0.5f * h * (1.0f + erff(h * 0.70710678118654752f));
}
__device__ __forceinline__ float act_silu(float h) {
    return h / (1.0f + __expf(-h));
}

// ---------------- launch 0: transpose + tf32-round BOTH weights ---------------
__global__ void tp_kernel(const float* __restrict__ W1,
                          const float* __restrict__ W2) {
    __shared__ float s[32][33];
    int z = blockIdx.z, w = z >> 3, e = z & 7;
    const float* Ws = w ? W2 : W1;
    float* Wd = w ? g_w2t : g_w1t;
    int R = w ? D_FF : D_MODEL;
    int C = w ? D_MODEL : D_FF;
    int cx = w ? blockIdx.y : blockIdx.x;
    int ry = w ? blockIdx.x : blockIdx.y;
    int c0 = cx * 32, r0 = ry * 32;
    int tx = threadIdx.x, ty = threadIdx.y;
    const float* Wb = Ws + (size_t)e * R * C;
    float* Wtb = Wd + (size_t)e * R * C;
#pragma unroll
    for (int j = 0; j < 4; j++)
        s[ty + 8 * j][tx] = Wb[(size_t)(r0 + ty + 8 * j) * C + c0 + tx];
    __syncthreads();
#pragma unroll
    for (int j = 0; j < 4; j++)
        Wtb[(size_t)(c0 + ty + 8 * j) * R + r0 + tx] =
            __uint_as_float(f2tf(s[tx][ty + 8 * j]));
}

// ---------------- launch 1: gate (fp32 exact) + tf32-round x -------------------
__global__ void gate_kernel(const float* __restrict__ x,
                            const float* __restrict__ Wg,
                            const float* __restrict__ bg) {
    int tid = threadIdx.x, wid = tid >> 5, lane = tid & 31;
    int t = blockIdx.x * 8 + wid;
    const float* xr = x + (size_t)t * D_MODEL;
    float acc[8] = {0, 0, 0, 0, 0, 0, 0, 0};
    for (int d = lane; d < D_MODEL; d += 32) {
        float xv = xr[d];
        const float4* w = (const float4*)(Wg + d * 8);
        float4 w0 = w[0], w1 = w[1];
        acc[0] += xv * w0.x; acc[1] += xv * w0.y;
        acc[2] += xv * w0.z; acc[3] += xv * w0.w;
        acc[4] += xv * w1.x; acc[5] += xv * w1.y;
        acc[6] += xv * w1.z; acc[7] += xv * w1.w;
    }
#pragma unroll
    for (int o = 16; o > 0; o >>= 1)
#pragma unroll
        for (int e = 0; e < 8; e++)
            acc[e] += __shfl_xor_sync(0xffffffffu, acc[e], o);
    if (lane == 0) {
        float v0 = -1e30f, v1 = -1e30f;
        int i0 = 0, i1 = 0;
#pragma unroll
        for (int e = 0; e < 8; e++) {
            float v = acc[e] + bg[e];
            if (v > v0) { v1 = v0; i1 = i0; v0 = v; i0 = e; }
            else if (v > v1) { v1 = v; i1 = e; }
        }
        float e1 = expf(v1 - v0);
        float inv = 1.0f / (1.0f + e1);
        g_tokE[t * 2]     = i0; g_tokW[t * 2]     = inv;
        g_tokE[t * 2 + 1] = i1; g_tokW[t * 2 + 1] = e1 * inv;
    }
    size_t base = (size_t)blockIdx.x * 8 * (D_MODEL / 4);
    const float4* xs = (const float4*)x + base;
    float4* xd = (float4*)g_xr + base;
#pragma unroll
    for (int i = 0; i < 8; i++) {
        float4 v = xs[tid + i * 256];
        v.x = __uint_as_float(f2tf(v.x));
        v.y = __uint_as_float(f2tf(v.y));
        v.z = __uint_as_float(f2tf(v.z));
        v.w = __uint_as_float(f2tf(v.w));
        xd[tid + i * 256] = v;
    }
}

// ---------------- launch 2: route (histogram + plan + scatter, 1 block) --------
__global__ void route_kernel() {
    __shared__ int sc[NE], scur[NE];
    int tid = threadIdx.x;
    if (tid < NE) sc[tid] = 0;
    for (int r = tid; r < MAXROWS; r += 1024) g_rowtok[r] = -1;
    __syncthreads();
    for (int i = tid; i < T_TOK * 2; i += 1024) atomicAdd(&sc[g_tokE[i]], 1);
    __syncthreads();
    if (tid == 0) {
        int ofs = 0;
        for (int e = 0; e < NE; e++) {
            scur[e] = ofs;
            int ntl = (sc[e] + 127) >> 7;
            int t0 = ofs >> 7;
            for (int j = 0; j < ntl; j++) g_tileE[t0 + j] = e;
            ofs += ntl << 7;
        }
        for (int t = ofs >> 7; t < MAXTILES; t++) g_tileE[t] = -1;
    }
    __syncthreads();
    for (int i = tid; i < T_TOK * 2; i += 1024) {
        int e = g_tokE[i];
        int row = atomicAdd(&scur[e], 1);
        g_loc[i] = row;
        g_rowtok[row] = i >> 1;
    }
}

// ---------------- launches 3/4: TF32 GEMM, 128 thr, 4 warps of 64x64 -----------
// A smem [128][36] words (m-major), B smem [128][36] words (k-major).
// ldmatrix.x4 both operands; 2 CTAs/SM (smem 108KB, <=256 regs) so the two
// CTAs' barrier/scoreboard bubbles are mutually overlapped.
template <int KTOT, int NTOT, bool FFN1_>
__global__ __launch_bounds__(128, 2) void ffn_mma(const float* __restrict__ bias) {
    constexpr int NT = NTOT / 128;
    constexpr int NC = KTOT / 32;

    int bid = blockIdx.x;
    int gid = bid / (8 * NT), rem = bid % (8 * NT);
    int mt = gid * 8 + (rem & 7);
    int nt = rem >> 3;
    int e = g_tileE[mt];
    if (e < 0) return;

    extern __shared__ unsigned smv[];
    uint32_t sb = smem_u32(smv);

    int tid = threadIdx.x, lane = tid & 31, wid = tid >> 5;
    int wm = wid >> 1, wn = wid & 1;     // 2 x 2 warp grid, warp tile 64x64
    int lr = lane >> 2, lc = lane & 3;
    int m0 = mt * 128, n0 = nt * 128;

    const float* Bt = FFN1_ ? g_w1t : g_w2t;
    const float* Bb = Bt + (size_t)e * D_MODEL * D_FF + (size_t)n0 * KTOT;
    float* Out = FFN1_ ? g_act : g_y;

    // ---- producer: A 1024 granules -> 8/thread, B 1024 -> 8/thread ----
    int rA = tid >> 3, qA = tid & 7;      // rA 0..15, rows rA + 16*i
    const float* srcA[8];
    unsigned amask = 0;
    uint32_t dA0 = (uint32_t)(rA * 144 + qA * 16);
#pragma unroll
    for (int i = 0; i < 8; i++) {
        int r = rA + 16 * i;
        if (FFN1_) {
            int tok = g_rowtok[m0 + r];
            if (tok >= 0) amask |= 1u << i;
            srcA[i] = g_xr + (size_t)(tok >= 0 ? tok : 0) * KTOT + qA * 4;
        } else {
            amask |= 1u << i;
            srcA[i] = g_act + (size_t)(m0 + r) * KTOT + qA * 4;
        }
    }
    const float* srcB0 = Bb + (size_t)rA * KTOT + qA * 4;
    uint32_t dB0 = (uint32_t)AB + dA0;

    auto issue = [&](int c) {
        if (c >= NC) return;
        uint32_t s0 = sb + (uint32_t)(c % NSTAGE) * STAGE_BYTES;
        int k0 = c * 32;
#pragma unroll
        for (int i = 0; i < 8; i++)
            CP_ASYNC16Z(s0 + dA0 + (uint32_t)i * 2304, srcA[i] + k0,
                        ((amask >> i) & 1u) * 16u);
        const float* bp = srcB0 + k0;
#pragma unroll
        for (int i = 0; i < 8; i++)
            CP_ASYNC16(s0 + dB0 + (uint32_t)i * 2304, bp + (size_t)i * 16 * KTOT);
    };

    // ---- consumer ldmatrix addressing (warp 64x64) ----
    int aRow = wm * 64 + ((lane >> 3) & 1) * 8 + (lane & 7);
    uint32_t aOff = (uint32_t)(aRow * 36 + ((lane >> 4) & 1) * 4) * 4;
    int bRow = wn * 64 + ((lane >> 4) & 1) * 8 + (lane & 7);
    uint32_t bOff = (uint32_t)AB + (uint32_t)(bRow * 36 + ((lane >> 3) & 1) * 4) * 4;

    float acc[4][8][4];
#pragma unroll
    for (int i = 0; i < 4; i++)
#pragma unroll
        for (int j = 0; j < 8; j++)
#pragma unroll
            for (int k = 0; k < 4; k++) acc[i][j][k] = 0.0f;

    unsigned fa[2][4][4], fb[2][4][4];

    issue(0); CP_COMMIT();
    issue(1); CP_COMMIT();

    for (int c = 0; c < NC; c++) {
        CP_WAIT1();
        __syncthreads();
        issue(c + 2);
        CP_COMMIT();

        uint32_t st = sb + (uint32_t)(c % NSTAGE) * STAGE_BYTES;
        uint32_t sA = st + aOff;
        uint32_t sB = st + bOff;
#pragma unroll
        for (int mf = 0; mf < 4; mf++) LDSM4(fa[0][mf], sA + mf * 2304);
#pragma unroll
        for (int p = 0; p < 4; p++)  LDSM4(fb[0][p], sB + p * 2304);
#pragma unroll
        for (int ks = 0; ks < 4; ks++) {
            int cur = ks & 1, nxt = cur ^ 1;
            if (ks < 3) {
                uint32_t kadd = (uint32_t)(ks + 1) * 32;
#pragma unroll
                for (int mf = 0; mf < 4; mf++) LDSM4(fa[nxt][mf], sA + mf * 2304 + kadd);
#pragma unroll
                for (int p = 0; p < 4; p++)  LDSM4(fb[nxt][p], sB + p * 2304 + kadd);
            }
#pragma unroll
            for (int nf = 0; nf < 8; nf++) {
                unsigned b0 = fb[cur][nf >> 1][(nf & 1) * 2];
                unsigned b1 = fb[cur][nf >> 1][(nf & 1) * 2 + 1];
#pragma unroll
                for (int mf = 0; mf < 4; mf++)
                    mma8(acc[mf][nf], fa[cur][mf], b0, b1);
            }
        }
    }

    // ---- epilogue: bias + activation (+tf32 re-round for FFN1) ----
    bool isGelu = !(e & 1);
    const float* bb = bias + (size_t)e * NTOT + n0;
#pragma unroll
    for (int mf = 0; mf < 4; mf++) {
#pragma unroll
        for (int nf = 0; nf < 8; nf++) {
            int row = m0 + wm * 64 + mf * 16 + lr;
            int colL = wn * 64 + nf * 8 + 2 * lc;
            float b0v = bb[colL], b1v = bb[colL + 1];
            float v00 = acc[mf][nf][0] + b0v;
            float v01 = acc[mf][nf][1] + b1v;
            float v10 = acc[mf][nf][2] + b0v;
            float v11 = acc[mf][nf][3] + b1v;
            if (FFN1_) {
                if (isGelu) {
                    v00 = act_gelu(v00); v01 = act_gelu(v01);
                    v10 = act_gelu(v10); v11 = act_gelu(v11);
                } else {
                    v00 = act_silu(v00); v01 = act_silu(v01);
                    v10 = act_silu(v10); v11 = act_silu(v11);
                }
                v00 = __uint_as_float(f2tf(v00));
                v01 = __uint_as_float(f2tf(v01));
                v10 = __uint_as_float(f2tf(v10));
                v11 = __uint_as_float(f2tf(v11));
            }
            float* op = Out + (size_t)row * NTOT + n0 + colL;
            *(float2*)op = make_float2(v00, v01);
            *(float2*)(op + (size_t)8 * NTOT) = make_float2(v10, v11);
        }
    }
}

// ---------------- launch 5: combine --------------------------------------------
__global__ void combine_kernel(float* __restrict__ out) {
    int t = blockIdx.x, c = threadIdx.x;
    float w0 = g_tokW[t * 2], w1 = g_tokW[t * 2 + 1];
    int l0 = g_loc[t * 2], l1 = g_loc[t * 2 + 1];
    const float4 y0 = *(const float4*)(g_y + (size_t)l0 * D_MODEL + c * 4);
    const float4 y1 = *(const float4*)(g_y + (size_t)l1 * D_MODEL + c * 4);
    float4 o;
    o.x = w0 * y0.x + w1 * y1.x;
    o.y = w0 * y0.y + w1 * y1.y;
    o.z = w0 * y0.z + w1 * y1.z;
    o.w = w0 * y0.w + w1 * y1.w;
    *(float4*)(out + (size_t)t * D_MODEL + c * 4) = o;
}

// ---------------- host launcher -------------------------------------------------
extern "C" void kernel_launch(void* const* d_in, const int* in_sizes, int n_in,
                              void* d_out, int out_size) {
    const float* x  = (const float*)d_in[0];
    const float* W1 = (const float*)d_in[1];
    const float* b1 = (const float*)d_in[2];
    const float* W2 = (const float*)d_in[3];
    const float* b2 = (const float*)d_in[4];
    const float* Wg = (const float*)d_in[5];
    const float* bg = (const float*)d_in[6];
    float* out = (float*)d_out;

    cudaFuncSetAttribute(ffn_mma<D_MODEL, D_FF, true>,
                         cudaFuncAttributeMaxDynamicSharedMemorySize, SMEM_TOTAL);
    cudaFuncSetAttribute(ffn_mma<D_FF, D_MODEL, false>,
                         cudaFuncAttributeMaxDynamicSharedMemorySize, SMEM_TOTAL);

    tp_kernel<<<dim3(128, 32, 16), dim3(32, 8)>>>(W1, W2);       // 0
    gate_kernel<<<T_TOK / 8, 256>>>(x, Wg, bg);                  // 1
    route_kernel<<<1, 1024>>>();                                 // 2
    ffn_mma<D_MODEL, D_FF, true>                                 // 3
        <<<MAXTILES * (D_FF / 128), 128, SMEM_TOTAL>>>(b1);
    ffn_mma<D_FF, D_MODEL, false>                                // 4
        <<<MAXTILES * (D_MODEL / 128), 128, SMEM_TOTAL>>>(b2);
    combine_kernel<<<T_TOK, 256>>>(out);                         // 5
}

// round 11
// speedup vs baseline: 1.3288x; 1.1975x over previous
#include <cuda_runtime.h>
#include <math.h>
#include <stdint.h>

#define D_MODEL 1024
#define D_FF    4096
#define NE      8
#define T_TOK   4096
#define MAXROWS 9216      // 8192 rows + 8 experts * 128-pad
#define MAXTILES 72

// GEMM tiling: CTA 128(M) x 128(N) x 32(K), 128 thr, 4 warps (2x2) of 64x64.
// 3-stage cp.async; smem 108KB/CTA -> 2 CTAs/SM for cross-CTA overlap.
#define NSTAGE 3
#define AW     4608                 // A stage words: 128 rows * 36
#define BWRD   4608                 // B stage words: 128 rows * 36 (k-major)
#define AB     (AW * 4)             // 18432 B
#define STAGE_BYTES ((AW + BWRD) * 4)      // 36864 B
#define SMEM_TOTAL (NSTAGE * STAGE_BYTES)  // 110592 B

// ---------------- scratch (static device memory: allocation-free) -------------
__device__ float g_act[(size_t)MAXROWS * D_FF];      // FFN1 acts (tf32-rounded)
__device__ float g_y[(size_t)MAXROWS * D_MODEL];     // FFN2 outputs (fp32)
__device__ float g_xr[(size_t)T_TOK * D_MODEL];      // x, tf32-rounded, token order
__device__ float g_w1t[(size_t)NE * D_FF * D_MODEL]; // W1^T [E][F][D] (k-major, rounded)
__device__ float g_w2t[(size_t)NE * D_MODEL * D_FF]; // W2^T [E][D][F] (k-major, rounded)
__device__ int   g_rowtok[MAXROWS];
__device__ int   g_tileE[MAXTILES];
__device__ int   g_tokE[T_TOK * 2];
__device__ float g_tokW[T_TOK * 2];
__device__ int   g_loc[T_TOK * 2];

// ---------------- helpers ----------------------------------------------------
__device__ __forceinline__ unsigned f2tf(float f) {
    unsigned u;
    asm("cvt.rna.tf32.f32 %0, %1;" : "=r"(u) : "f"(f));
    return u;
}
__device__ __forceinline__ uint32_t smem_u32(const void* p) {
    uint32_t a;
    asm("{ .reg .u64 t; cvta.to.shared.u64 t, %1; cvt.u32.u64 %0, t; }" : "=r"(a) : "l"(p));
    return a;
}
#define CP_ASYNC16(dst, src) \
    asm volatile("cp.async.cg.shared.global [%0], [%1], 16;" :: "r"(dst), "l"(src) : "memory")
#define CP_ASYNC16Z(dst, src, sz) \
    asm volatile("cp.async.cg.shared.global [%0], [%1], 16, %2;" :: "r"(dst), "l"(src), "r"(sz) : "memory")
#define CP_COMMIT() asm volatile("cp.async.commit_group;" ::: "memory")
#define CP_WAIT0()  asm volatile("cp.async.wait_group 0;" ::: "memory")
#define LDSM4(r, a)                                                               \
    asm volatile("ldmatrix.sync.aligned.m8n8.x4.shared.b16 {%0,%1,%2,%3}, [%4];" \
        : "=r"((r)[0]), "=r"((r)[1]), "=r"((r)[2]), "=r"((r)[3]) : "r"(a))

__device__ __forceinline__ void mma8(float (&d)[4], const unsigned (&a)[4],
                                     unsigned b0, unsigned b1) {
    asm volatile(
        "mma.sync.aligned.m16n8k8.row.col.f32.tf32.tf32.f32 "
        "{%0,%1,%2,%3}, {%4,%5,%6,%7}, {%8,%9}, {%0,%1,%2,%3};\n"
        : "+f"(d[0]), "+f"(d[1]), "+f"(d[2]), "+f"(d[3])
        : "r"(a[0]), "r"(a[1]), "r"(a[2]), "r"(a[3]), "r"(b0), "r"(b1));
}

__device__ __forceinline__ float act_gelu(float h) {
    return 0.5f * h * (1.0f + erff(h * 0.70710678118654752f));
}
__device__ __forceinline__ float act_silu(float h) {
    return h / (1.0f + __expf(-h));
}

// ---------------- launch 0: transpose + tf32-round BOTH weights ---------------
__global__ void tp_kernel(const float* __restrict__ W1,
                          const float* __restrict__ W2) {
    __shared__ float s[32][33];
    int z = blockIdx.z, w = z >> 3, e = z & 7;
    const float* Ws = w ? W2 : W1;
    float* Wd = w ? g_w2t : g_w1t;
    int R = w ? D_FF : D_MODEL;
    int C = w ? D_MODEL : D_FF;
    int cx = w ? blockIdx.y : blockIdx.x;
    int ry = w ? blockIdx.x : blockIdx.y;
    int c0 = cx * 32, r0 = ry * 32;
    int tx = threadIdx.x, ty = threadIdx.y;
    const float* Wb = Ws + (size_t)e * R * C;
    float* Wtb = Wd + (size_t)e * R * C;
#pragma unroll
    for (int j = 0; j < 4; j++)
        s[ty + 8 * j][tx] = Wb[(size_t)(r0 + ty + 8 * j) * C + c0 + tx];
    __syncthreads();
#pragma unroll
    for (int j = 0; j < 4; j++)
        Wtb[(size_t)(c0 + ty + 8 * j) * R + r0 + tx] =
            __uint_as_float(f2tf(s[tx][ty + 8 * j]));
}

// ---------------- launch 1: gate (fp32 exact) + tf32-round x -------------------
__global__ void gate_kernel(const float* __restrict__ x,
                            const float* __restrict__ Wg,
                            const float* __restrict__ bg) {
    int tid = threadIdx.x, wid = tid >> 5, lane = tid & 31;
    int t = blockIdx.x * 8 + wid;
    const float* xr = x + (size_t)t * D_MODEL;
    float acc[8] = {0, 0, 0, 0, 0, 0, 0, 0};
    for (int d = lane; d < D_MODEL; d += 32) {
        float xv = xr[d];
        const float4* w = (const float4*)(Wg + d * 8);
        float4 w0 = w[0], w1 = w[1];
        acc[0] += xv * w0.x; acc[1] += xv * w0.y;
        acc[2] += xv * w0.z; acc[3] += xv * w0.w;
        acc[4] += xv * w1.x; acc[5] += xv * w1.y;
        acc[6] += xv * w1.z; acc[7] += xv * w1.w;
    }
#pragma unroll
    for (int o = 16; o > 0; o >>= 1)
#pragma unroll
        for (int e = 0; e < 8; e++)
            acc[e] += __shfl_xor_sync(0xffffffffu, acc[e], o);
    if (lane == 0) {
        float v0 = -1e30f, v1 = -1e30f;
        int i0 = 0, i1 = 0;
#pragma unroll
        for (int e = 0; e < 8; e++) {
            float v = acc[e] + bg[e];
            if (v > v0) { v1 = v0; i1 = i0; v0 = v; i0 = e; }
            else if (v > v1) { v1 = v; i1 = e; }
        }
        float e1 = expf(v1 - v0);
        float inv = 1.0f / (1.0f + e1);
        g_tokE[t * 2]     = i0; g_tokW[t * 2]     = inv;
        g_tokE[t * 2 + 1] = i1; g_tokW[t * 2 + 1] = e1 * inv;
    }
    size_t base = (size_t)blockIdx.x * 8 * (D_MODEL / 4);
    const float4* xs = (const float4*)x + base;
    float4* xd = (float4*)g_xr + base;
#pragma unroll
    for (int i = 0; i < 8; i++) {
        float4 v = xs[tid + i * 256];
        v.x = __uint_as_float(f2tf(v.x));
        v.y = __uint_as_float(f2tf(v.y));
        v.z = __uint_as_float(f2tf(v.z));
        v.w = __uint_as_float(f2tf(v.w));
        xd[tid + i * 256] = v;
    }
}

// ---------------- launch 2: route (histogram + plan + scatter, 1 block) --------
__global__ void route_kernel() {
    __shared__ int sc[NE], scur[NE];
    int tid = threadIdx.x;
    if (tid < NE) sc[tid] = 0;
    for (int r = tid; r < MAXROWS; r += 1024) g_rowtok[r] = -1;
    __syncthreads();
    for (int i = tid; i < T_TOK * 2; i += 1024) atomicAdd(&sc[g_tokE[i]], 1);
    __syncthreads();
    if (tid == 0) {
        int ofs = 0;
        for (int e = 0; e < NE; e++) {
            scur[e] = ofs;
            int ntl = (sc[e] + 127) >> 7;
            int t0 = ofs >> 7;
            for (int j = 0; j < ntl; j++) g_tileE[t0 + j] = e;
            ofs += ntl << 7;
        }
        for (int t = ofs >> 7; t < MAXTILES; t++) g_tileE[t] = -1;
    }
    __syncthreads();
    for (int i = tid; i < T_TOK * 2; i += 1024) {
        int e = g_tokE[i];
        int row = atomicAdd(&scur[e], 1);
        g_loc[i] = row;
        g_rowtok[row] = i >> 1;
    }
}

// ---------------- launches 3/4: TF32 GEMM, 128 thr, 4 warps of 64x64 -----------
// wait_group 0 at each chunk boundary => stage c+1 provably resident during
// compute of chunk c => ks3 prefetches next chunk's ks0 fragments, so MMAs
// start immediately after the barrier (no post-barrier LDSM latency chain).
template <int KTOT, int NTOT, bool FFN1_>
__global__ __launch_bounds__(128, 2) void ffn_mma(const float* __restrict__ bias) {
    constexpr int NT = NTOT / 128;
    constexpr int NC = KTOT / 32;

    int bid = blockIdx.x;
    int gid = bid / (8 * NT), rem = bid % (8 * NT);
    int mt = gid * 8 + (rem & 7);
    int nt = rem >> 3;
    int e = g_tileE[mt];
    if (e < 0) return;

    extern __shared__ unsigned smv[];
    uint32_t sb = smem_u32(smv);

    int tid = threadIdx.x, lane = tid & 31, wid = tid >> 5;
    int wm = wid >> 1, wn = wid & 1;     // 2 x 2 warp grid, warp tile 64x64
    int lr = lane >> 2, lc = lane & 3;
    int m0 = mt * 128, n0 = nt * 128;

    const float* Bt = FFN1_ ? g_w1t : g_w2t;
    const float* Bb = Bt + (size_t)e * D_MODEL * D_FF + (size_t)n0 * KTOT;
    float* Out = FFN1_ ? g_act : g_y;

    // ---- producer: A 1024 granules -> 8/thread, B 1024 -> 8/thread ----
    int rA = tid >> 3, qA = tid & 7;      // rA 0..15, rows rA + 16*i
    const float* srcA[8];
    unsigned amask = 0;
    uint32_t dA0 = (uint32_t)(rA * 144 + qA * 16);
#pragma unroll
    for (int i = 0; i < 8; i++) {
        int r = rA + 16 * i;
        if (FFN1_) {
            int tok = g_rowtok[m0 + r];
            if (tok >= 0) amask |= 1u << i;
            srcA[i] = g_xr + (size_t)(tok >= 0 ? tok : 0) * KTOT + qA * 4;
        } else {
            amask |= 1u << i;
            srcA[i] = g_act + (size_t)(m0 + r) * KTOT + qA * 4;
        }
    }
    const float* srcB0 = Bb + (size_t)rA * KTOT + qA * 4;
    uint32_t dB0 = (uint32_t)AB + dA0;

    auto issue = [&](int c, uint32_t s0) {
        int k0 = c * 32;
#pragma unroll
        for (int i = 0; i < 8; i++)
            CP_ASYNC16Z(s0 + dA0 + (uint32_t)i * 2304, srcA[i] + k0,
                        ((amask >> i) & 1u) * 16u);
        const float* bp = srcB0 + k0;
#pragma unroll
        for (int i = 0; i < 8; i++)
            CP_ASYNC16(s0 + dB0 + (uint32_t)i * 2304, bp + (size_t)i * 16 * KTOT);
    };

    // ---- consumer ldmatrix addressing (warp 64x64) ----
    int aRow = wm * 64 + ((lane >> 3) & 1) * 8 + (lane & 7);
    uint32_t aOff = (uint32_t)(aRow * 36 + ((lane >> 4) & 1) * 4) * 4;
    int bRow = wn * 64 + ((lane >> 4) & 1) * 8 + (lane & 7);
    uint32_t bOff = (uint32_t)AB + (uint32_t)(bRow * 36 + ((lane >> 3) & 1) * 4) * 4;

    float acc[4][8][4];
#pragma unroll
    for (int i = 0; i < 4; i++)
#pragma unroll
        for (int j = 0; j < 8; j++)
#pragma unroll
            for (int k = 0; k < 4; k++) acc[i][j][k] = 0.0f;

    unsigned fa[2][4][4], fb[2][4][4];

    // rotating stage bases: stCur = chunk c, stNxt = c+1, stWr = c+2 (write)
    uint32_t stCur = sb, stNxt = sb + STAGE_BYTES, stWr = sb + 2 * STAGE_BYTES;

    issue(0, stCur); CP_COMMIT();
    issue(1, stNxt); CP_COMMIT();
    CP_WAIT0();
    __syncthreads();
    // preload chunk 0 ks0 fragments
#pragma unroll
    for (int mf = 0; mf < 4; mf++) LDSM4(fa[0][mf], stCur + aOff + mf * 2304);
#pragma unroll
    for (int p = 0; p < 4; p++)  LDSM4(fb[0][p], stCur + bOff + p * 2304);

    for (int c = 0; c < NC; c++) {
        if (c + 2 < NC) { issue(c + 2, stWr); }
        CP_COMMIT();

        uint32_t sA = stCur + aOff;
        uint32_t sB = stCur + bOff;
#pragma unroll
        for (int ks = 0; ks < 4; ks++) {
            int cur = ks & 1, nxt = cur ^ 1;
            if (ks < 3) {
                uint32_t kadd = (uint32_t)(ks + 1) * 32;
#pragma unroll
                for (int mf = 0; mf < 4; mf++) LDSM4(fa[nxt][mf], sA + mf * 2304 + kadd);
#pragma unroll
                for (int p = 0; p < 4; p++)  LDSM4(fb[nxt][p], sB + p * 2304 + kadd);
            } else if (c + 1 < NC) {
                // cross-chunk prefetch: next chunk's ks0 from stage c+1 (resident)
#pragma unroll
                for (int mf = 0; mf < 4; mf++) LDSM4(fa[nxt][mf], stNxt + aOff + mf * 2304);
#pragma unroll
                for (int p = 0; p < 4; p++)  LDSM4(fb[nxt][p], stNxt + bOff + p * 2304);
            }
#pragma unroll
            for (int nf = 0; nf < 8; nf++) {
                unsigned b0 = fb[cur][nf >> 1][(nf & 1) * 2];
                unsigned b1 = fb[cur][nf >> 1][(nf & 1) * 2 + 1];
#pragma unroll
                for (int mf = 0; mf < 4; mf++)
                    mma8(acc[mf][nf], fa[cur][mf], b0, b1);
            }
        }
        CP_WAIT0();
        __syncthreads();
        uint32_t t0 = stCur; stCur = stNxt; stNxt = stWr; stWr = t0;
    }

    // ---- epilogue: bias + activation (+tf32 re-round for FFN1) ----
    bool isGelu = !(e & 1);
    const float* bb = bias + (size_t)e * NTOT + n0;
#pragma unroll
    for (int mf = 0; mf < 4; mf++) {
#pragma unroll
        for (int nf = 0; nf < 8; nf++) {
            int row = m0 + wm * 64 + mf * 16 + lr;
            int colL = wn * 64 + nf * 8 + 2 * lc;
            float b0v = bb[colL], b1v = bb[colL + 1];
            float v00 = acc[mf][nf][0] + b0v;
            float v01 = acc[mf][nf][1] + b1v;
            float v10 = acc[mf][nf][2] + b0v;
            float v11 = acc[mf][nf][3] + b1v;
            if (FFN1_) {
                if (isGelu) {
                    v00 = act_gelu(v00); v01 = act_gelu(v01);
                    v10 = act_gelu(v10); v11 = act_gelu(v11);
                } else {
                    v00 = act_silu(v00); v01 = act_silu(v01);
                    v10 = act_silu(v10); v11 = act_silu(v11);
                }
                v00 = __uint_as_float(f2tf(v00));
                v01 = __uint_as_float(f2tf(v01));
                v10 = __uint_as_float(f2tf(v10));
                v11 = __uint_as_float(f2tf(v11));
            }
            float* op = Out + (size_t)row * NTOT + n0 + colL;
            *(float2*)op = make_float2(v00, v01);
            *(float2*)(op + (size_t)8 * NTOT) = make_float2(v10, v11);
        }
    }
}

// ---------------- launch 5: combine --------------------------------------------
__global__ void combine_kernel(float* __restrict__ out) {
    int t = blockIdx.x, c = threadIdx.x;
    float w0 = g_tokW[t * 2], w1 = g_tokW[t * 2 + 1];
    int l0 = g_loc[t * 2], l1 = g_loc[t * 2 + 1];
    const float4 y0 = *(const float4*)(g_y + (size_t)l0 * D_MODEL + c * 4);
    const float4 y1 = *(const float4*)(g_y + (size_t)l1 * D_MODEL + c * 4);
    float4 o;
    o.x = w0 * y0.x + w1 * y1.x;
    o.y = w0 * y0.y + w1 * y1.y;
    o.z = w0 * y0.z + w1 * y1.z;
    o.w = w0 * y0.w + w1 * y1.w;
    *(float4*)(out + (size_t)t * D_MODEL + c * 4) = o;
}

// ---------------- host launcher -------------------------------------------------
extern "C" void kernel_launch(void* const* d_in, const int* in_sizes, int n_in,
                              void* d_out, int out_size) {
    const float* x  = (const float*)d_in[0];
    const float* W1 = (const float*)d_in[1];
    const float* b1 = (const float*)d_in[2];
    const float* W2 = (const float*)d_in[3];
    const float* b2 = (const float*)d_in[4];
    const float* Wg = (const float*)d_in[5];
    const float* bg = (const float*)d_in[6];
    float* out = (float*)d_out;

    cudaFuncSetAttribute(ffn_mma<D_MODEL, D_FF, true>,
                         cudaFuncAttributeMaxDynamicSharedMemorySize, SMEM_TOTAL);
    cudaFuncSetAttribute(ffn_mma<D_FF, D_MODEL, false>,
                         cudaFuncAttributeMaxDynamicSharedMemorySize, SMEM_TOTAL);

    tp_kernel<<<dim3(128, 32, 16), dim3(32, 8)>>>(W1, W2);       // 0
    gate_kernel<<<T_TOK / 8, 256>>>(x, Wg, bg);                  // 1
    route_kernel<<<1, 1024>>>();                                 // 2
    ffn_mma<D_MODEL, D_FF, true>                                 // 3
        <<<MAXTILES * (D_FF / 128), 128, SMEM_TOTAL>>>(b1);
    ffn_mma<D_FF, D_MODEL, false>                                // 4
        <<<MAXTILES * (D_MODEL / 128), 128, SMEM_TOTAL>>>(b2);
    combine_kernel<<<T_TOK, 256>>>(out);                         // 5
}

// round 16
// speedup vs baseline: 1.3409x; 1.0091x over previous
#include <cuda_runtime.h>
#include <math.h>
#include <stdint.h>

#define D_MODEL 1024
#define D_FF    4096
#define NE      8
#define T_TOK   4096
#define MAXROWS 9216      // 8192 rows + 8 experts * 128-pad
#define MAXTILES 72

// GEMM tiling: CTA 128(M) x 128(N) x 32(K), 128 thr, 4 warps (2x2) of 64x64.
// A stage m-major [128][36] (ldmatrix), B stage n-major [32][136] (scalar LDS
// + cvt.rna -> no weight transpose prepass needed). 3-stage cp.async,
// 2 CTAs/SM.
#define NSTAGE 3
#define AW     4608                  // A stage words: 128 rows * 36
#define BWRD   4352                  // B stage words: 32 k-rows * 136
#define ABB    (AW * 4)              // 18432 B: B offset within stage
#define STAGE_BYTES ((AW + BWRD) * 4)       // 35840 B
#define SMEM_TOTAL (NSTAGE * STAGE_BYTES)   // 107520 B

// ---------------- scratch (static device memory: allocation-free) -------------
__device__ float g_act[(size_t)MAXROWS * D_FF];      // FFN1 acts (tf32-rounded)
__device__ float g_y[(size_t)MAXROWS * D_MODEL];     // FFN2 outputs (fp32)
__device__ float g_xr[(size_t)T_TOK * D_MODEL];      // x, tf32-rounded
__device__ int   g_rowtok[MAXROWS];
__device__ int   g_tileE[MAXTILES];
__device__ int   g_tokE[T_TOK * 2];
__device__ float g_tokW[T_TOK * 2];
__device__ int   g_loc[T_TOK * 2];

// ---------------- helpers ----------------------------------------------------
__device__ __forceinline__ unsigned f2tf(float f) {
    unsigned u;
    asm("cvt.rna.tf32.f32 %0, %1;" : "=r"(u) : "f"(f));
    return u;
}
__device__ __forceinline__ uint32_t smem_u32(const void* p) {
    uint32_t a;
    asm("{ .reg .u64 t; cvta.to.shared.u64 t, %1; cvt.u32.u64 %0, t; }" : "=r"(a) : "l"(p));
    return a;
}
#define CP_ASYNC16(dst, src) \
    asm volatile("cp.async.cg.shared.global [%0], [%1], 16;" :: "r"(dst), "l"(src) : "memory")
#define CP_ASYNC16Z(dst, src, sz) \
    asm volatile("cp.async.cg.shared.global [%0], [%1], 16, %2;" :: "r"(dst), "l"(src), "r"(sz) : "memory")
#define CP_COMMIT() asm volatile("cp.async.commit_group;" ::: "memory")
#define CP_WAIT0()  asm volatile("cp.async.wait_group 0;" ::: "memory")
#define LDSM4(r, a)                                                               \
    asm volatile("ldmatrix.sync.aligned.m8n8.x4.shared.b16 {%0,%1,%2,%3}, [%4];" \
        : "=r"((r)[0]), "=r"((r)[1]), "=r"((r)[2]), "=r"((r)[3]) : "r"(a))
#define LDS32(r, a) \
    asm volatile("ld.shared.b32 %0, [%1];" : "=r"(r) : "r"(a))

__device__ __forceinline__ void mma8(float (&d)[4], const unsigned (&a)[4],
                                     unsigned b0, unsigned b1) {
    asm volatile(
        "mma.sync.aligned.m16n8k8.row.col.f32.tf32.tf32.f32 "
        "{%0,%1,%2,%3}, {%4,%5,%6,%7}, {%8,%9}, {%0,%1,%2,%3};\n"
        : "+f"(d[0]), "+f"(d[1]), "+f"(d[2]), "+f"(d[3])
        : "r"(a[0]), "r"(a[1]), "r"(a[2]), "r"(a[3]), "r"(b0), "r"(b1));
}

__device__ __forceinline__ float act_gelu(float h) {
    return 0.5f * h * (1.0f + erff(h * 0.70710678118654752f));
}
__device__ __forceinline__ float act_silu(float h) {
    return h / (1.0f + __expf(-h));
}

// ---------------- launch 0: gate (fp32 exact) + tf32-round x -------------------
__global__ void gate_kernel(const float* __restrict__ x,
                            const float* __restrict__ Wg,
                            const float* __restrict__ bg) {
    int tid = threadIdx.x, wid = tid >> 5, lane = tid & 31;
    int t = blockIdx.x * 8 + wid;
    const float* xr = x + (size_t)t * D_MODEL;
    float acc[8] = {0, 0, 0, 0, 0, 0, 0, 0};
    for (int d = lane; d < D_MODEL; d += 32) {
        float xv = xr[d];
        const float4* w = (const float4*)(Wg + d * 8);
        float4 w0 = w[0], w1 = w[1];
        acc[0] += xv * w0.x; acc[1] += xv * w0.y;
        acc[2] += xv * w0.z; acc[3] += xv * w0.w;
        acc[4] += xv * w1.x; acc[5] += xv * w1.y;
        acc[6] += xv * w1.z; acc[7] += xv * w1.w;
    }
#pragma unroll
    for (int o = 16; o > 0; o >>= 1)
#pragma unroll
        for (int e = 0; e < 8; e++)
            acc[e] += __shfl_xor_sync(0xffffffffu, acc[e], o);
    if (lane == 0) {
        float v0 = -1e30f, v1 = -1e30f;
        int i0 = 0, i1 = 0;
#pragma unroll
        for (int e = 0; e < 8; e++) {
            float v = acc[e] + bg[e];
            if (v > v0) { v1 = v0; i1 = i0; v0 = v; i0 = e; }
            else if (v > v1) { v1 = v; i1 = e; }
        }
        float e1 = expf(v1 - v0);
        float inv = 1.0f / (1.0f + e1);
        g_tokE[t * 2]     = i0; g_tokW[t * 2]     = inv;
        g_tokE[t * 2 + 1] = i1; g_tokW[t * 2 + 1] = e1 * inv;
    }
    size_t base = (size_t)blockIdx.x * 8 * (D_MODEL / 4);
    const float4* xs = (const float4*)x + base;
    float4* xd = (float4*)g_xr + base;
#pragma unroll
    for (int i = 0; i < 8; i++) {
        float4 v = xs[tid + i * 256];
        v.x = __uint_as_float(f2tf(v.x));
        v.y = __uint_as_float(f2tf(v.y));
        v.z = __uint_as_float(f2tf(v.z));
        v.w = __uint_as_float(f2tf(v.w));
        xd[tid + i * 256] = v;
    }
}

// ---------------- launch 1: route (histogram + plan + scatter, 1 block) --------
__global__ void route_kernel() {
    __shared__ int sc[NE], scur[NE];
    int tid = threadIdx.x;
    if (tid < NE) sc[tid] = 0;
    for (int r = tid; r < MAXROWS; r += 1024) g_rowtok[r] = -1;
    __syncthreads();
    for (int i = tid; i < T_TOK * 2; i += 1024) atomicAdd(&sc[g_tokE[i]], 1);
    __syncthreads();
    if (tid == 0) {
        int ofs = 0;
        for (int e = 0; e < NE; e++) {
            scur[e] = ofs;
            int ntl = (sc[e] + 127) >> 7;
            int t0 = ofs >> 7;
            for (int j = 0; j < ntl; j++) g_tileE[t0 + j] = e;
            ofs += ntl << 7;
        }
        for (int t = ofs >> 7; t < MAXTILES; t++) g_tileE[t] = -1;
    }
    __syncthreads();
    for (int i = tid; i < T_TOK * 2; i += 1024) {
        int e = g_tokE[i];
        int row = atomicAdd(&scur[e], 1);
        g_loc[i] = row;
        g_rowtok[row] = i >> 1;
    }
}

// ---------------- launches 2/3: TF32 GEMM, 128 thr, 4 warps of 64x64 -----------
// B consumed n-major straight from the ORIGINAL weights (no transpose prepass):
// scalar LDS (conflict-free) + cvt.rna in-register -> numerics identical to the
// pre-rounded path. A via ldmatrix as before. wait_group 0 boundary + ks3
// cross-chunk prefetch (R11 structure).
template <int KTOT, int NTOT, bool FFN1_>
__global__ __launch_bounds__(128, 2) void ffn_mma(const float* __restrict__ W,
                                                  const float* __restrict__ bias) {
    constexpr int NT = NTOT / 128;
    constexpr int NC = KTOT / 32;

    int bid = blockIdx.x;
    int gid = bid / (8 * NT), rem = bid % (8 * NT);
    int mt = gid * 8 + (rem & 7);
    int nt = rem >> 3;
    int e = g_tileE[mt];
    if (e < 0) return;

    extern __shared__ unsigned smv[];
    uint32_t sb = smem_u32(smv);

    int tid = threadIdx.x, lane = tid & 31, wid = tid >> 5;
    int wm = wid >> 1, wn = wid & 1;     // 2 x 2 warp grid, warp tile 64x64
    int lr = lane >> 2, lc = lane & 3;
    int m0 = mt * 128, n0 = nt * 128;

    // W layout: [E][KTOT][NTOT] row-major (k-rows of NTOT) for both FFN1/FFN2.
    const float* Bb = W + (size_t)e * D_MODEL * D_FF + n0;
    float* Out = FFN1_ ? g_act : g_y;

    // ---- producer A: 1024 granules -> 8/thread (ldmatrix layout, stride 36) ----
    int rA = tid >> 3, qA = tid & 7;      // rA 0..15, rows rA + 16*i
    const float* srcA[8];
    unsigned amask = 0;
    uint32_t dA0 = (uint32_t)(rA * 144 + qA * 16);
#pragma unroll
    for (int i = 0; i < 8; i++) {
        int r = rA + 16 * i;
        if (FFN1_) {
            int tok = g_rowtok[m0 + r];
            if (tok >= 0) amask |= 1u << i;
            srcA[i] = g_xr + (size_t)(tok >= 0 ? tok : 0) * KTOT + qA * 4;
        } else {
            amask |= 1u << i;
            srcA[i] = g_act + (size_t)(m0 + r) * KTOT + qA * 4;
        }
    }
    // ---- producer B: 1024 granules n-major -> 8/thread ----
    // granule g = tid + i*128: k = (tid>>5) + 4*i, nq = tid & 31
    int krB = tid >> 5, nqB = tid & 31;
    const float* srcB0 = Bb + (size_t)krB * NTOT + nqB * 4;
    uint32_t dB0 = (uint32_t)ABB + (uint32_t)(krB * 136 + nqB * 4) * 4;

    auto issue = [&](int c, uint32_t s0) {
        int k0 = c * 32;
#pragma unroll
        for (int i = 0; i < 8; i++)
            CP_ASYNC16Z(s0 + dA0 + (uint32_t)i * 2304, srcA[i] + k0,
                        ((amask >> i) & 1u) * 16u);
        const float* bp = srcB0 + (size_t)k0 * NTOT;
#pragma unroll
        for (int i = 0; i < 8; i++)
            CP_ASYNC16(s0 + dB0 + (uint32_t)i * 4 * 136 * 4,
                       bp + (size_t)i * 4 * NTOT);
    };

    // ---- consumer addressing ----
    int aRow = wm * 64 + ((lane >> 3) & 1) * 8 + (lane & 7);
    uint32_t aOff = (uint32_t)(aRow * 36 + ((lane >> 4) & 1) * 4) * 4;
    // B scalar: value(ks,nf,j) at ABB + ((ks*8 + lc + j*4)*136 + wn*64+nf*8+lr)*4
    uint32_t bOff = (uint32_t)ABB + (uint32_t)(lc * 136 + wn * 64 + lr) * 4;

    float acc[4][8][4];
#pragma unroll
    for (int i = 0; i < 4; i++)
#pragma unroll
        for (int j = 0; j < 8; j++)
#pragma unroll
            for (int k = 0; k < 4; k++) acc[i][j][k] = 0.0f;

    unsigned fa[2][4][4], fbw[2][16];

    // loadB: 16 B-words (8 nf x {b0,b1}) for k-slice ks at stage base st
    auto loadB = [&](unsigned* dst, uint32_t st, int ks) {
        uint32_t base = st + bOff + (uint32_t)(ks * 8 * 136) * 4;
#pragma unroll
        for (int nf = 0; nf < 8; nf++) {
            unsigned v0, v1;
            LDS32(v0, base + (uint32_t)(nf * 8) * 4);
            LDS32(v1, base + (uint32_t)(4 * 136 + nf * 8) * 4);
            dst[nf * 2]     = f2tf(__uint_as_float(v0));
            dst[nf * 2 + 1] = f2tf(__uint_as_float(v1));
        }
    };

    // rotating stage bases: stCur = chunk c, stNxt = c+1, stWr = c+2 (write)
    uint32_t stCur = sb, stNxt = sb + STAGE_BYTES, stWr = sb + 2 * STAGE_BYTES;

    issue(0, stCur); CP_COMMIT();
    issue(1, stNxt); CP_COMMIT();
    CP_WAIT0();
    __syncthreads();
    // preload chunk 0 ks0 fragments
#pragma unroll
    for (int mf = 0; mf < 4; mf++) LDSM4(fa[0][mf], stCur + aOff + mf * 2304);
    loadB(fbw[0], stCur, 0);

    for (int c = 0; c < NC; c++) {
        if (c + 2 < NC) { issue(c + 2, stWr); }
        CP_COMMIT();

        uint32_t sA = stCur + aOff;
#pragma unroll
        for (int ks = 0; ks < 4; ks++) {
            int cur = ks & 1, nxt = cur ^ 1;
            if (ks < 3) {
                uint32_t kadd = (uint32_t)(ks + 1) * 32;
#pragma unroll
                for (int mf = 0; mf < 4; mf++) LDSM4(fa[nxt][mf], sA + mf * 2304 + kadd);
                loadB(fbw[nxt], stCur, ks + 1);
            } else if (c + 1 < NC) {
                // cross-chunk prefetch: next chunk's ks0 from stage c+1 (resident)
#pragma unroll
                for (int mf = 0; mf < 4; mf++) LDSM4(fa[nxt][mf], stNxt + aOff + mf * 2304);
                loadB(fbw[nxt], stNxt, 0);
            }
#pragma unroll
            for (int nf = 0; nf < 8; nf++) {
                unsigned b0 = fbw[cur][nf * 2];
                unsigned b1 = fbw[cur][nf * 2 + 1];
#pragma unroll
                for (int mf = 0; mf < 4; mf++)
                    mma8(acc[mf][nf], fa[cur][mf], b0, b1);
            }
        }
        CP_WAIT0();
        __syncthreads();
        uint32_t t0 = stCur; stCur = stNxt; stNxt = stWr; stWr = t0;
    }

    // ---- epilogue: bias + activation (+tf32 re-round for FFN1) ----
    bool isGelu = !(e & 1);
    const float* bb = bias + (size_t)e * NTOT + n0;
#pragma unroll
    for (int mf = 0; mf < 4; mf++) {
#pragma unroll
        for (int nf = 0; nf < 8; nf++) {
            int row = m0 + wm * 64 + mf * 16 + lr;
            int colL = wn * 64 + nf * 8 + 2 * lc;
            float b0v = bb[colL], b1v = bb[colL + 1];
            float v00 = acc[mf][nf][0] + b0v;
            float v01 = acc[mf][nf][1] + b1v;
            float v10 = acc[mf][nf][2] + b0v;
            float v11 = acc[mf][nf][3] + b1v;
            if (FFN1_) {
                if (isGelu) {
                    v00 = act_gelu(v00); v01 = act_gelu(v01);
                    v10 = act_gelu(v10); v11 = act_gelu(v11);
                } else {
                    v00 = act_silu(v00); v01 = act_silu(v01);
                    v10 = act_silu(v10); v11 = act_silu(v11);
                }
                v00 = __uint_as_float(f2tf(v00));
                v01 = __uint_as_float(f2tf(v01));
                v10 = __uint_as_float(f2tf(v10));
                v11 = __uint_as_float(f2tf(v11));
            }
            float* op = Out + (size_t)row * NTOT + n0 + colL;
            *(float2*)op = make_float2(v00, v01);
            *(float2*)(op + (size_t)8 * NTOT) = make_float2(v10, v11);
        }
    }
}

// ---------------- launch 4: combine --------------------------------------------
__global__ void combine_kernel(float* __restrict__ out) {
    int t = blockIdx.x, c = threadIdx.x;
    float w0 = g_tokW[t * 2], w1 = g_tokW[t * 2 + 1];
    int l0 = g_loc[t * 2], l1 = g_loc[t * 2 + 1];
    const float4 y0 = *(const float4*)(g_y + (size_t)l0 * D_MODEL + c * 4);
    const float4 y1 = *(const float4*)(g_y + (size_t)l1 * D_MODEL + c * 4);
    float4 o;
    o.x = w0 * y0.x + w1 * y1.x;
    o.y = w0 * y0.y + w1 * y1.y;
    o.z = w0 * y0.z + w1 * y1.z;
    o.w = w0 * y0.w + w1 * y1.w;
    *(float4*)(out + (size_t)t * D_MODEL + c * 4) = o;
}

// ---------------- host launcher -------------------------------------------------
extern "C" void kernel_launch(void* const* d_in, const int* in_sizes, int n_in,
                              void* d_out, int out_size) {
    const float* x  = (const float*)d_in[0];
    const float* W1 = (const float*)d_in[1];
    const float* b1 = (const float*)d_in[2];
    const float* W2 = (const float*)d_in[3];
    const float* b2 = (const float*)d_in[4];
    const float* Wg = (const float*)d_in[5];
    const float* bg = (const float*)d_in[6];
    float* out = (float*)d_out;

    cudaFuncSetAttribute(ffn_mma<D_MODEL, D_FF, true>,
                         cudaFuncAttributeMaxDynamicSharedMemorySize, SMEM_TOTAL);
    cudaFuncSetAttribute(ffn_mma<D_FF, D_MODEL, false>,
                         cudaFuncAttributeMaxDynamicSharedMemorySize, SMEM_TOTAL);

    gate_kernel<<<T_TOK / 8, 256>>>(x, Wg, bg);                  // 0
    route_kernel<<<1, 1024>>>();                                 // 1
    ffn_mma<D_MODEL, D_FF, true>                                 // 2
        <<<MAXTILES * (D_FF / 128), 128, SMEM_TOTAL>>>(W1, b1);
    ffn_mma<D_FF, D_MODEL, false>                                // 3
        <<<MAXTILES * (D_MODEL / 128), 128, SMEM_TOTAL>>>(W2, b2);
    combine_kernel<<<T_TOK, 256>>>(out);                         // 4
}

// round 17
// speedup vs baseline: 1.4328x; 1.0685x over previous
#include <cuda_runtime.h>
#include <math.h>
#include <stdint.h>

#define D_MODEL 1024
#define D_FF    4096
#define NE      8
#define T_TOK   4096
#define MAXROWS 9216      // 8192 rows + 8 experts * 128-pad
#define MAXTILES 72

// Compensation for tf32-truncation bias on the B operand (weights fed raw):
// mean relative shrink per GEMM = 2^-11 * E[1/mantissa] ~= 3.5e-4.
#define CSCALE 1.00035f

// GEMM tiling: CTA 128(M) x 128(N) x 32(K), 128 thr, 4 warps (2x2) of 64x64.
// A stage m-major [128][36] (ldmatrix), B stage n-major [32][136] (scalar LDS,
// raw fp32 -> HW tf32 truncation, bias pre-compensated on A). 3-stage
// cp.async, 2 CTAs/SM.
#define NSTAGE 3
#define AW     4608                  // A stage words: 128 rows * 36
#define BWRD   4352                  // B stage words: 32 k-rows * 136
#define ABB    (AW * 4)              // 18432 B: B offset within stage
#define STAGE_BYTES ((AW + BWRD) * 4)       // 35840 B
#define SMEM_TOTAL (NSTAGE * STAGE_BYTES)   // 107520 B

// ---------------- scratch (static device memory: allocation-free) -------------
__device__ float g_act[(size_t)MAXROWS * D_FF];      // FFN1 acts (tf32-rounded, +CSCALE)
__device__ float g_y[(size_t)MAXROWS * D_MODEL];     // FFN2 outputs (fp32)
__device__ float g_xr[(size_t)T_TOK * D_MODEL];      // x * CSCALE, tf32-rounded
__device__ int   g_rowtok[MAXROWS];
__device__ int   g_tileE[MAXTILES];
__device__ int   g_tokE[T_TOK * 2];
__device__ float g_tokW[T_TOK * 2];
__device__ int   g_loc[T_TOK * 2];

// ---------------- helpers ----------------------------------------------------
__device__ __forceinline__ unsigned f2tf(float f) {
    unsigned u;
    asm("cvt.rna.tf32.f32 %0, %1;" : "=r"(u) : "f"(f));
    return u;
}
__device__ __forceinline__ uint32_t smem_u32(const void* p) {
    uint32_t a;
    asm("{ .reg .u64 t; cvta.to.shared.u64 t, %1; cvt.u32.u64 %0, t; }" : "=r"(a) : "l"(p));
    return a;
}
#define CP_ASYNC16(dst, src) \
    asm volatile("cp.async.cg.shared.global [%0], [%1], 16;" :: "r"(dst), "l"(src) : "memory")
#define CP_ASYNC16Z(dst, src, sz) \
    asm volatile("cp.async.cg.shared.global [%0], [%1], 16, %2;" :: "r"(dst), "l"(src), "r"(sz) : "memory")
#define CP_COMMIT() asm volatile("cp.async.commit_group;" ::: "memory")
#define CP_WAIT0()  asm volatile("cp.async.wait_group 0;" ::: "memory")
#define LDSM4(r, a)                                                               \
    asm volatile("ldmatrix.sync.aligned.m8n8.x4.shared.b16 {%0,%1,%2,%3}, [%4];" \
        : "=r"((r)[0]), "=r"((r)[1]), "=r"((r)[2]), "=r"((r)[3]) : "r"(a))
#define LDS32(r, a) \
    asm volatile("ld.shared.b32 %0, [%1];" : "=r"(r) : "r"(a))

// NOTE: non-volatile — pure register dataflow; lets the compiler interleave
// MMAs with B loads.
__device__ __forceinline__ void mma8(float (&d)[4], const unsigned (&a)[4],
                                     unsigned b0, unsigned b1) {
    asm("mma.sync.aligned.m16n8k8.row.col.f32.tf32.tf32.f32 "
        "{%0,%1,%2,%3}, {%4,%5,%6,%7}, {%8,%9}, {%0,%1,%2,%3};\n"
        : "+f"(d[0]), "+f"(d[1]), "+f"(d[2]), "+f"(d[3])
        : "r"(a[0]), "r"(a[1]), "r"(a[2]), "r"(a[3]), "r"(b0), "r"(b1));
}

__device__ __forceinline__ float act_gelu(float h) {
    return 0.5f * h * (1.0f + erff(h * 0.70710678118654752f));
}
__device__ __forceinline__ float act_silu(float h) {
    return h / (1.0f + __expf(-h));
}

// ---------------- launch 0: gate (fp32 exact) + tf32-round x*CSCALE ------------
__global__ void gate_kernel(const float* __restrict__ x,
                            const float* __restrict__ Wg,
                            const float* __restrict__ bg) {
    int tid = threadIdx.x, wid = tid >> 5, lane = tid & 31;
    int t = blockIdx.x * 8 + wid;
    const float* xr = x + (size_t)t * D_MODEL;
    float acc[8] = {0, 0, 0, 0, 0, 0, 0, 0};
    for (int d = lane; d < D_MODEL; d += 32) {
        float xv = xr[d];
        const float4* w = (const float4*)(Wg + d * 8);
        float4 w0 = w[0], w1 = w[1];
        acc[0] += xv * w0.x; acc[1] += xv * w0.y;
        acc[2] += xv * w0.z; acc[3] += xv * w0.w;
        acc[4] += xv * w1.x; acc[5] += xv * w1.y;
        acc[6] += xv * w1.z; acc[7] += xv * w1.w;
    }
#pragma unroll
    for (int o = 16; o > 0; o >>= 1)
#pragma unroll
        for (int e = 0; e < 8; e++)
            acc[e] += __shfl_xor_sync(0xffffffffu, acc[e], o);
    if (lane == 0) {
        float v0 = -1e30f, v1 = -1e30f;
        int i0 = 0, i1 = 0;
#pragma unroll
        for (int e = 0; e < 8; e++) {
            float v = acc[e] + bg[e];
            if (v > v0) { v1 = v0; i1 = i0; v0 = v; i0 = e; }
            else if (v > v1) { v1 = v; i1 = e; }
        }
        float e1 = expf(v1 - v0);
        float inv = 1.0f / (1.0f + e1);
        g_tokE[t * 2]     = i0; g_tokW[t * 2]     = inv;
        g_tokE[t * 2 + 1] = i1; g_tokW[t * 2 + 1] = e1 * inv;
    }
    size_t base = (size_t)blockIdx.x * 8 * (D_MODEL / 4);
    const float4* xs = (const float4*)x + base;
    float4* xd = (float4*)g_xr + base;
#pragma unroll
    for (int i = 0; i < 8; i++) {
        float4 v = xs[tid + i * 256];
        v.x = __uint_as_float(f2tf(v.x * CSCALE));
        v.y = __uint_as_float(f2tf(v.y * CSCALE));
        v.z = __uint_as_float(f2tf(v.z * CSCALE));
        v.w = __uint_as_float(f2tf(v.w * CSCALE));
        xd[tid + i * 256] = v;
    }
}

// ---------------- launch 1: route (histogram + plan + scatter, 1 block) --------
__global__ void route_kernel() {
    __shared__ int sc[NE], scur[NE];
    int tid = threadIdx.x;
    if (tid < NE) sc[tid] = 0;
    for (int r = tid; r < MAXROWS; r += 1024) g_rowtok[r] = -1;
    __syncthreads();
    for (int i = tid; i < T_TOK * 2; i += 1024) atomicAdd(&sc[g_tokE[i]], 1);
    __syncthreads();
    if (tid == 0) {
        int ofs = 0;
        for (int e = 0; e < NE; e++) {
            scur[e] = ofs;
            int ntl = (sc[e] + 127) >> 7;
            int t0 = ofs >> 7;
            for (int j = 0; j < ntl; j++) g_tileE[t0 + j] = e;
            ofs += ntl << 7;
        }
        for (int t = ofs >> 7; t < MAXTILES; t++) g_tileE[t] = -1;
    }
    __syncthreads();
    for (int i = tid; i < T_TOK * 2; i += 1024) {
        int e = g_tokE[i];
        int row = atomicAdd(&scur[e], 1);
        g_loc[i] = row;
        g_rowtok[row] = i >> 1;
    }
}

// ---------------- launches 2/3: TF32 GEMM, 128 thr, 4 warps of 64x64 -----------
// B consumed n-major straight from the ORIGINAL weights: scalar LDS, raw fp32
// bits fed to the tf32 MMA (HW truncates low 13 mantissa bits). The resulting
// -0.5ulp systematic shrink is pre-compensated by CSCALE on the A operand.
// A via ldmatrix. wait_group 0 boundary + ks3 cross-chunk prefetch.
template <int KTOT, int NTOT, bool FFN1_>
__global__ __launch_bounds__(128, 2) void ffn_mma(const float* __restrict__ W,
                                                  const float* __restrict__ bias) {
    constexpr int NT = NTOT / 128;
    constexpr int NC = KTOT / 32;

    int bid = blockIdx.x;
    int gid = bid / (8 * NT), rem = bid % (8 * NT);
    int mt = gid * 8 + (rem & 7);
    int nt = rem >> 3;
    int e = g_tileE[mt];
    if (e < 0) return;

    extern __shared__ unsigned smv[];
    uint32_t sb = smem_u32(smv);

    int tid = threadIdx.x, lane = tid & 31, wid = tid >> 5;
    int wm = wid >> 1, wn = wid & 1;     // 2 x 2 warp grid, warp tile 64x64
    int lr = lane >> 2, lc = lane & 3;
    int m0 = mt * 128, n0 = nt * 128;

    // W layout: [E][KTOT][NTOT] row-major (k-rows of NTOT) for both FFN1/FFN2.
    const float* Bb = W + (size_t)e * D_MODEL * D_FF + n0;
    float* Out = FFN1_ ? g_act : g_y;

    // ---- producer A: 1024 granules -> 8/thread (ldmatrix layout, stride 36) ----
    int rA = tid >> 3, qA = tid & 7;      // rA 0..15, rows rA + 16*i
    const float* srcA[8];
    unsigned amask = 0;
    uint32_t dA0 = (uint32_t)(rA * 144 + qA * 16);
#pragma unroll
    for (int i = 0; i < 8; i++) {
        int r = rA + 16 * i;
        if (FFN1_) {
            int tok = g_rowtok[m0 + r];
            if (tok >= 0) amask |= 1u << i;
            srcA[i] = g_xr + (size_t)(tok >= 0 ? tok : 0) * KTOT + qA * 4;
        } else {
            amask |= 1u << i;
            srcA[i] = g_act + (size_t)(m0 + r) * KTOT + qA * 4;
        }
    }
    // ---- producer B: 1024 granules n-major -> 8/thread ----
    // granule g = tid + i*128: k = (tid>>5) + 4*i, nq = tid & 31
    int krB = tid >> 5, nqB = tid & 31;
    const float* srcB0 = Bb + (size_t)krB * NTOT + nqB * 4;
    uint32_t dB0 = (uint32_t)ABB + (uint32_t)(krB * 136 + nqB * 4) * 4;

    auto issue = [&](int c, uint32_t s0) {
        int k0 = c * 32;
#pragma unroll
        for (int i = 0; i < 8; i++)
            CP_ASYNC16Z(s0 + dA0 + (uint32_t)i * 2304, srcA[i] + k0,
                        ((amask >> i) & 1u) * 16u);
        const float* bp = srcB0 + (size_t)k0 * NTOT;
#pragma unroll
        for (int i = 0; i < 8; i++)
            CP_ASYNC16(s0 + dB0 + (uint32_t)i * 4 * 136 * 4,
                       bp + (size_t)i * 4 * NTOT);
    };

    // ---- consumer addressing ----
    int aRow = wm * 64 + ((lane >> 3) & 1) * 8 + (lane & 7);
    uint32_t aOff = (uint32_t)(aRow * 36 + ((lane >> 4) & 1) * 4) * 4;
    // B scalar: value(ks,nf,j) at ABB + ((ks*8 + lc + j*4)*136 + wn*64+nf*8+lr)*4
    uint32_t bOff = (uint32_t)ABB + (uint32_t)(lc * 136 + wn * 64 + lr) * 4;

    float acc[4][8][4];
#pragma unroll
    for (int i = 0; i < 4; i++)
#pragma unroll
        for (int j = 0; j < 8; j++)
#pragma unroll
            for (int k = 0; k < 4; k++) acc[i][j][k] = 0.0f;

    unsigned fa[2][4][4], fbw[2][16];

    // loadB: 16 raw fp32 B-words (8 nf x {b0,b1}) for k-slice ks at stage st
    auto loadB = [&](unsigned* dst, uint32_t st, int ks) {
        uint32_t base = st + bOff + (uint32_t)(ks * 8 * 136) * 4;
#pragma unroll
        for (int nf = 0; nf < 8; nf++) {
            LDS32(dst[nf * 2],     base + (uint32_t)(nf * 8) * 4);
            LDS32(dst[nf * 2 + 1], base + (uint32_t)(4 * 136 + nf * 8) * 4);
        }
    };

    // rotating stage bases: stCur = chunk c, stNxt = c+1, stWr = c+2 (write)
    uint32_t stCur = sb, stNxt = sb + STAGE_BYTES, stWr = sb + 2 * STAGE_BYTES;

    issue(0, stCur); CP_COMMIT();
    issue(1, stNxt); CP_COMMIT();
    CP_WAIT0();
    __syncthreads();
    // preload chunk 0 ks0 fragments
#pragma unroll
    for (int mf = 0; mf < 4; mf++) LDSM4(fa[0][mf], stCur + aOff + mf * 2304);
    loadB(fbw[0], stCur, 0);

    for (int c = 0; c < NC; c++) {
        if (c + 2 < NC) { issue(c + 2, stWr); }
        CP_COMMIT();

        uint32_t sA = stCur + aOff;
#pragma unroll
        for (int ks = 0; ks < 4; ks++) {
            int cur = ks & 1, nxt = cur ^ 1;
            if (ks < 3) {
                uint32_t kadd = (uint32_t)(ks + 1) * 32;
#pragma unroll
                for (int mf = 0; mf < 4; mf++) LDSM4(fa[nxt][mf], sA + mf * 2304 + kadd);
                loadB(fbw[nxt], stCur, ks + 1);
            } else if (c + 1 < NC) {
                // cross-chunk prefetch: next chunk's ks0 from stage c+1 (resident)
#pragma unroll
                for (int mf = 0; mf < 4; mf++) LDSM4(fa[nxt][mf], stNxt + aOff + mf * 2304);
                loadB(fbw[nxt], stNxt, 0);
            }
#pragma unroll
            for (int nf = 0; nf < 8; nf++) {
                unsigned b0 = fbw[cur][nf * 2];
                unsigned b1 = fbw[cur][nf * 2 + 1];
#pragma unroll
                for (int mf = 0; mf < 4; mf++)
                    mma8(acc[mf][nf], fa[cur][mf], b0, b1);
            }
        }
        CP_WAIT0();
        __syncthreads();
        uint32_t t0 = stCur; stCur = stNxt; stNxt = stWr; stWr = t0;
    }

    // ---- epilogue: bias + activation; FFN1 also applies CSCALE (GEMM2
    // truncation pre-compensation) + tf32 re-round ----
    bool isGelu = !(e & 1);
    const float* bb = bias + (size_t)e * NTOT + n0;
#pragma unroll
    for (int mf = 0; mf < 4; mf++) {
#pragma unroll
        for (int nf = 0; nf < 8; nf++) {
            int row = m0 + wm * 64 + mf * 16 + lr;
            int colL = wn * 64 + nf * 8 + 2 * lc;
            float b0v = bb[colL], b1v = bb[colL + 1];
            float v00 = acc[mf][nf][0] + b0v;
            float v01 = acc[mf][nf][1] + b1v;
            float v10 = acc[mf][nf][2] + b0v;
            float v11 = acc[mf][nf][3] + b1v;
            if (FFN1_) {
                if (isGelu) {
                    v00 = act_gelu(v00); v01 = act_gelu(v01);
                    v10 = act_gelu(v10); v11 = act_gelu(v11);
                } else {
                    v00 = act_silu(v00); v01 = act_silu(v01);
                    v10 = act_silu(v10); v11 = act_silu(v11);
                }
                v00 = __uint_as_float(f2tf(v00 * CSCALE));
                v01 = __uint_as_float(f2tf(v01 * CSCALE));
                v10 = __uint_as_float(f2tf(v10 * CSCALE));
                v11 = __uint_as_float(f2tf(v11 * CSCALE));
            }
            float* op = Out + (size_t)row * NTOT + n0 + colL;
            *(float2*)op = make_float2(v00, v01);
            *(float2*)(op + (size_t)8 * NTOT) = make_float2(v10, v11);
        }
    }
}

// ---------------- launch 4: combine --------------------------------------------
__global__ void combine_kernel(float* __restrict__ out) {
    int t = blockIdx.x, c = threadIdx.x;
    float w0 = g_tokW[t * 2], w1 = g_tokW[t * 2 + 1];
    int l0 = g_loc[t * 2], l1 = g_loc[t * 2 + 1];
    const float4 y0 = *(const float4*)(g_y + (size_t)l0 * D_MODEL + c * 4);
    const float4 y1 = *(const float4*)(g_y + (size_t)l1 * D_MODEL + c * 4);
    float4 o;
    o.x = w0 * y0.x + w1 * y1.x;
    o.y = w0 * y0.y + w1 * y1.y;
    o.z = w0 * y0.z + w1 * y1.z;
    o.w = w0 * y0.w + w1 * y1.w;
    *(float4*)(out + (size_t)t * D_MODEL + c * 4) = o;
}

// ---------------- host launcher -------------------------------------------------
extern "C" void kernel_launch(void* const* d_in, const int* in_sizes, int n_in,
                              void* d_out, int out_size) {
    const float* x  = (const float*)d_in[0];
    const float* W1 = (const float*)d_in[1];
    const float* b1 = (const float*)d_in[2];
    const float* W2 = (const float*)d_in[3];
    const float* b2 = (const float*)d_in[4];
    const float* Wg = (const float*)d_in[5];
    const float* bg = (const float*)d_in[6];
    float* out = (float*)d_out;

    cudaFuncSetAttribute(ffn_mma<D_MODEL, D_FF, true>,
                         cudaFuncAttributeMaxDynamicSharedMemorySize, SMEM_TOTAL);
    cudaFuncSetAttribute(ffn_mma<D_FF, D_MODEL, false>,
                         cudaFuncAttributeMaxDynamicSharedMemorySize, SMEM_TOTAL);

    gate_kernel<<<T_TOK / 8, 256>>>(x, Wg, bg);                  // 0
    route_kernel<<<1, 1024>>>();                                 // 1
    ffn_mma<D_MODEL, D_FF, true>                                 // 2
        <<<MAXTILES * (D_FF / 128), 128, SMEM_TOTAL>>>(W1, b1);
    ffn_mma<D_FF, D_MODEL, false>                                // 3
        <<<MAXTILES * (D_MODEL / 128), 128, SMEM_TOTAL>>>(W2, b2);
    combine_kernel<<<T_TOK, 256>>>(out);                         // 4
}